// round 11
// baseline (speedup 1.0000x reference)
#include <cuda_runtime.h>
#include <cuda_bf16.h>
#include <cstdint>

// ---------------- problem constants ----------------
#define NNODES 50000
#define NEDGES 800000
#define HD     256
#define TD2    512
#define GDC    512
#define KLR    100
#define MB     391
#define WSLOT  (512 * 512)

// ---------------- static scratch ----------------
__device__ float g_x[NNODES * HD];
__device__ float g_h[NNODES * HD];
__device__ float g_t[NNODES * TD2];
__device__ __nv_bfloat16 g_xhi[NNODES * HD];
__device__ __nv_bfloat16 g_xlo[NNODES * HD];
__device__ __nv_bfloat16 g_chi[NNODES * GDC];
__device__ __nv_bfloat16 g_clo[NNODES * GDC];
__device__ __nv_bfloat16 g_wh[9 * WSLOT];
__device__ __nv_bfloat16 g_wl[9 * WSLOT];
__device__ float g_M[KLR * KLR];
__device__ float g_cs[2 * KLR];
__device__ float g_inv_nf;
__device__ float g_mean[HD];
__device__ float g_msq[HD];
__device__ float g_dis[NNODES];
__device__ int   g_deg[NNODES];
__device__ int   g_rowptr[NNODES + 1];
__device__ int   g_cur[NNODES];
__device__ int   g_colidx[NEDGES];
__device__ int   g_bsum[64];

// ---------------- PTX helpers ----------------
__device__ __forceinline__ uint32_t smem_u32(const void* p) {
    uint32_t a;
    asm("{ .reg .u64 t; cvta.to.shared.u64 t, %1; cvt.u32.u64 %0, t; }"
        : "=r"(a) : "l"(p));
    return a;
}

__device__ __forceinline__ void cp16(uint32_t dst, const void* src, int sz) {
    asm volatile("cp.async.cg.shared.global [%0], [%1], 16, %2;"
                 :: "r"(dst), "l"(src), "r"(sz) : "memory");
}

__device__ __forceinline__ void ldm_x4(uint32_t* r, uint32_t addr) {
    asm volatile("ldmatrix.sync.aligned.m8n8.x4.shared.b16 {%0,%1,%2,%3}, [%4];"
                 : "=r"(r[0]), "=r"(r[1]), "=r"(r[2]), "=r"(r[3]) : "r"(addr));
}

__device__ __forceinline__ void mma_bf16(float* d, const uint32_t* a,
                                         const uint32_t* b) {
    asm volatile(
        "mma.sync.aligned.m16n8k16.row.col.f32.bf16.bf16.f32 "
        "{%0,%1,%2,%3}, {%4,%5,%6,%7}, {%8,%9}, {%0,%1,%2,%3};"
        : "+f"(d[0]), "+f"(d[1]), "+f"(d[2]), "+f"(d[3])
        : "r"(a[0]), "r"(a[1]), "r"(a[2]), "r"(a[3]), "r"(b[0]), "r"(b[1]));
}

// ---------------- shared GEMM mainloop (round-6 proven config) ----------------
#define STAGE_BYTES 49152

#define GEMM_MAINLOOP(ACC)                                                     \
    extern __shared__ char dsm_raw[];                                          \
    uint32_t base0 = (smem_u32(dsm_raw) + 1023u) & ~1023u;                     \
    const int tid = threadIdx.x;                                               \
    const int wid = tid >> 5;                                                  \
    const int lane = tid & 31;                                                 \
    const int wm = wid & 3;                                                    \
    const int wn = wid >> 2;                                                   \
    const int row0 = blockIdx.y * 128;                                         \
    const int col0 = blockIdx.x * 64;                                          \
    const __nv_bfloat16* Bh0 = Bh + (size_t)col0 * K;                          \
    const __nv_bfloat16* Bl0 = Bl + (size_t)col0 * K;                          \
    const int nc = K >> 6;                                                     \
    float ACC[2][4][4];                                                        \
    _Pragma("unroll")                                                          \
    for (int mt = 0; mt < 2; mt++)                                             \
        _Pragma("unroll")                                                      \
        for (int nt = 0; nt < 4; nt++)                                         \
            _Pragma("unroll")                                                  \
            for (int q = 0; q < 4; q++) ACC[mt][nt][q] = 0.f;                  \
    auto load_chunk = [&](int c) {                                             \
        uint32_t sb = base0 + (uint32_t)(c & 1) * STAGE_BYTES;                 \
        int k0 = c << 6;                                                       \
        _Pragma("unroll 4")                                                    \
        for (int j = 0; j < 4; j++) {                                          \
            int i = tid + j * 256;                                             \
            int r = i >> 3, seg = i & 7;                                       \
            int off = r * 128 + seg * 16;                                      \
            uint32_t sw = (uint32_t)(off ^ ((off >> 3) & 0x70));               \
            int ga = row0 + r;                                                 \
            int ok = (ga < M) ? 16 : 0;                                        \
            if (ga >= M) ga = 0;                                               \
            size_t ao = (size_t)ga * K + k0 + seg * 8;                         \
            cp16(sb + sw,         Ah + ao, ok);                                \
            cp16(sb + 16384 + sw, Al + ao, ok);                                \
        }                                                                      \
        {                                                                      \
            int i = tid;                                                       \
            int r = i >> 3, seg = i & 7;                                       \
            int off = r * 128 + seg * 16;                                      \
            uint32_t sw = (uint32_t)(off ^ ((off >> 3) & 0x70));               \
            size_t bo = (size_t)r * K + k0 + seg * 8;                          \
            cp16(sb + 32768 + sw, Bh0 + bo, 16);                               \
            cp16(sb + 40960 + sw, Bl0 + bo, 16);                               \
        }                                                                      \
        {                                                                      \
            int i = tid + 256;                                                 \
            int r = i >> 3, seg = i & 7;                                       \
            int off = r * 128 + seg * 16;                                      \
            uint32_t sw = (uint32_t)(off ^ ((off >> 3) & 0x70));               \
            size_t bo = (size_t)r * K + k0 + seg * 8;                          \
            cp16(sb + 32768 + sw, Bh0 + bo, 16);                               \
            cp16(sb + 40960 + sw, Bl0 + bo, 16);                               \
        }                                                                      \
        asm volatile("cp.async.commit_group;" ::: "memory");                   \
    };                                                                         \
    const int a_off0 = (wm * 32 + (lane & 15)) * 128 + ((lane >> 4) << 4);     \
    const int b_off0 = (wn * 32 + ((lane >> 4) << 3) + (lane & 7)) * 128       \
                     + (((lane >> 3) & 1) << 4);                               \
    load_chunk(0);                                                             \
    for (int c = 0; c < nc; c++) {                                             \
        if (c + 1 < nc) {                                                      \
            load_chunk(c + 1);                                                 \
            asm volatile("cp.async.wait_group 1;" ::: "memory");               \
        } else {                                                               \
            asm volatile("cp.async.wait_group 0;" ::: "memory");               \
        }                                                                      \
        __syncthreads();                                                       \
        uint32_t sb = base0 + (uint32_t)(c & 1) * STAGE_BYTES;                 \
        _Pragma("unroll")                                                      \
        for (int kk = 0; kk < 4; kk++) {                                       \
            uint32_t ah[2][4], al[2][4], bh[2][4], bl[2][4];                   \
            _Pragma("unroll")                                                  \
            for (int mt = 0; mt < 2; mt++) {                                   \
                int off = a_off0 + mt * 2048 + kk * 32;                        \
                uint32_t sw = (uint32_t)(off ^ ((off >> 3) & 0x70));           \
                ldm_x4(ah[mt], sb + sw);                                       \
                ldm_x4(al[mt], sb + 16384 + sw);                               \
            }                                                                  \
            _Pragma("unroll")                                                  \
            for (int np = 0; np < 2; np++) {                                   \
                int off = b_off0 + np * 2048 + kk * 32;                        \
                uint32_t sw = (uint32_t)(off ^ ((off >> 3) & 0x70));           \
                ldm_x4(bh[np], sb + 32768 + sw);                               \
                ldm_x4(bl[np], sb + 40960 + sw);                               \
            }                                                                  \
            _Pragma("unroll")                                                  \
            for (int mt = 0; mt < 2; mt++)                                     \
                _Pragma("unroll")                                              \
                for (int nt = 0; nt < 4; nt++) {                               \
                    const uint32_t* bhp = &bh[nt >> 1][(nt & 1) * 2];          \
                    const uint32_t* blp = &bl[nt >> 1][(nt & 1) * 2];          \
                    mma_bf16(ACC[mt][nt], ah[mt], bhp);                        \
                    mma_bf16(ACC[mt][nt], ah[mt], blp);                        \
                    mma_bf16(ACC[mt][nt], al[mt], bhp);                        \
                }                                                              \
        }                                                                      \
        __syncthreads();                                                       \
    }

// ---------------- plain GEMM: C = act(A@B^T + bias), optional BN stats ------
__global__ void __launch_bounds__(256, 2)
mma_gemm(const __nv_bfloat16* __restrict__ Ah, const __nv_bfloat16* __restrict__ Al,
         const __nv_bfloat16* __restrict__ Bh, const __nv_bfloat16* __restrict__ Bl,
         const float* __restrict__ bias, float* __restrict__ C,
         int M, int K, int ldc, int nvalid, int relu, int bnstats) {
    GEMM_MAINLOOP(acc)
    __shared__ float s_red[128];
    if (bnstats) {
        if (tid < 128) s_red[tid] = 0.f;
        __syncthreads();
    }
    const int lcol = wn * 32 + (lane & 3) * 2;   // local col base (per nt add nt*8)
#pragma unroll
    for (int mt = 0; mt < 2; mt++) {
        int ra = row0 + wm * 32 + mt * 16 + (lane >> 2);
        int rb = ra + 8;
#pragma unroll
        for (int nt = 0; nt < 4; nt++) {
            int c0 = col0 + wn * 32 + nt * 8 + (lane & 3) * 2;
            float bv0 = 0.f, bv1 = 0.f;
            if (bias && c0 < nvalid) {
                bv0 = __ldg(&bias[c0]);
                bv1 = __ldg(&bias[c0 + 1]);
            }
            float v0 = acc[mt][nt][0] + bv0;
            float v1 = acc[mt][nt][1] + bv1;
            float v2 = acc[mt][nt][2] + bv0;
            float v3 = acc[mt][nt][3] + bv1;
            if (relu) {
                v0 = fmaxf(v0, 0.f); v1 = fmaxf(v1, 0.f);
                v2 = fmaxf(v2, 0.f); v3 = fmaxf(v3, 0.f);
            }
            if (ra < M) *(float2*)&C[(size_t)ra * ldc + c0] = make_float2(v0, v1);
            if (rb < M) *(float2*)&C[(size_t)rb * ldc + c0] = make_float2(v2, v3);
            if (bnstats) {
                float s0 = 0.f, s1 = 0.f, q0 = 0.f, q1 = 0.f;
                if (ra < M) { s0 += v0; s1 += v1; q0 += v0 * v0; q1 += v1 * v1; }
                if (rb < M) { s0 += v2; s1 += v3; q0 += v2 * v2; q1 += v3 * v3; }
                int l0 = lcol + nt * 8;
                atomicAdd(&s_red[l0], s0);
                atomicAdd(&s_red[l0 + 1], s1);
                atomicAdd(&s_red[64 + l0], q0);
                atomicAdd(&s_red[64 + l0 + 1], q1);
            }
        }
    }
    if (bnstats) {
        __syncthreads();
        if (tid < 64) {
            atomicAdd(&g_mean[col0 + tid], s_red[tid]);
            atomicAdd(&g_msq[col0 + tid], s_red[64 + tid]);
        }
    }
}

// ---------------- fused h+t GEMM (+ colsum of t cols 0..199) ----------------
__global__ void __launch_bounds__(256, 2)
mma_gemm_fused(const __nv_bfloat16* __restrict__ Ah, const __nv_bfloat16* __restrict__ Al,
               const __nv_bfloat16* __restrict__ Bh, const __nv_bfloat16* __restrict__ Bl,
               const float* __restrict__ bias2,
               float* __restrict__ C1, float* __restrict__ C2,
               int M, int K) {
    GEMM_MAINLOOP(acc)
    __shared__ float s_red[64];
    float* C;
    int ldc, rel, cbase, nval;
    const float* bias;
    if (col0 < 256) {
        C = C1; ldc = HD; rel = 0; bias = nullptr; cbase = col0; nval = HD;
    } else {
        C = C2; ldc = TD2; rel = 1; bias = bias2; cbase = col0 - 256; nval = 400;
    }
    const int docs = (col0 >= 256) && (cbase < 200);
    if (docs) {
        if (tid < 64) s_red[tid] = 0.f;
        __syncthreads();
    }
    const int lcol = wn * 32 + (lane & 3) * 2;
#pragma unroll
    for (int mt = 0; mt < 2; mt++) {
        int ra = row0 + wm * 32 + mt * 16 + (lane >> 2);
        int rb = ra + 8;
#pragma unroll
        for (int nt = 0; nt < 4; nt++) {
            int c0 = cbase + wn * 32 + nt * 8 + (lane & 3) * 2;
            float bv0 = 0.f, bv1 = 0.f;
            if (bias && c0 < nval) {
                bv0 = __ldg(&bias[c0]);
                bv1 = __ldg(&bias[c0 + 1]);
            }
            float v0 = acc[mt][nt][0] + bv0;
            float v1 = acc[mt][nt][1] + bv1;
            float v2 = acc[mt][nt][2] + bv0;
            float v3 = acc[mt][nt][3] + bv1;
            if (rel) {
                v0 = fmaxf(v0, 0.f); v1 = fmaxf(v1, 0.f);
                v2 = fmaxf(v2, 0.f); v3 = fmaxf(v3, 0.f);
            }
            if (ra < M) *(float2*)&C[(size_t)ra * ldc + c0] = make_float2(v0, v1);
            if (rb < M) *(float2*)&C[(size_t)rb * ldc + c0] = make_float2(v2, v3);
            if (docs) {
                float s0 = 0.f, s1 = 0.f;
                if (ra < M) { s0 += v0; s1 += v1; }
                if (rb < M) { s0 += v2; s1 += v3; }
                int l0 = lcol + nt * 8;
                atomicAdd(&s_red[l0], s0);
                atomicAdd(&s_red[l0 + 1], s1);
            }
        }
    }
    if (docs) {
        __syncthreads();
        if (tid < 64) {
            int c = cbase + tid;
            if (c < 200) atomicAdd(&g_cs[c], s_red[tid]);
        }
    }
}

// ---------------- conversion kernels ----------------
__global__ void xsplit_kernel(const float* __restrict__ x, long n) {
    long i = (long)blockIdx.x * blockDim.x + threadIdx.x;
    if (i < n) {
        float v = x[i];
        __nv_bfloat16 hi = __float2bfloat16(v);
        g_xhi[i] = hi;
        g_xlo[i] = __float2bfloat16(v - __bfloat162float(hi));
    }
}

__global__ void wsplit_kernel(const float* __restrict__ W, int K, int N,
                              int Nout, int Kpad, int slot, int row0) {
    int i = blockIdx.x * blockDim.x + threadIdx.x;
    if (i < Nout * Kpad) {
        int n = i / Kpad, k = i - n * Kpad;
        float v = (n < N && k < K) ? W[(size_t)k * N + n] : 0.f;
        __nv_bfloat16 hi = __float2bfloat16(v);
        size_t o = (size_t)slot * WSLOT + (size_t)(row0 + n) * Kpad + k;
        g_wh[o] = hi;
        g_wl[o] = __float2bfloat16(v - __bfloat162float(hi));
    }
}

__global__ void padzero_kernel() {
    int v = blockIdx.x, c = threadIdx.x;
    if (c < GDC - 456) {
        size_t o = (size_t)v * GDC + 456 + c;
        g_chi[o] = __float2bfloat16(0.f);
        g_clo[o] = __float2bfloat16(0.f);
    }
}

// ---------------- graph setup ----------------
__global__ void zero_deg_kernel() {
    int i = blockIdx.x * blockDim.x + threadIdx.x;
    if (i < NNODES) g_deg[i] = 0;
}

__global__ void count_deg_kernel(const int* __restrict__ dst) {
    for (int e = blockIdx.x * blockDim.x + threadIdx.x; e < NEDGES;
         e += gridDim.x * blockDim.x)
        atomicAdd(&g_deg[dst[e]], 1);
}

__global__ void scan1_kernel() {
    __shared__ int s[1024];
    int tid = threadIdx.x;
    int i = blockIdx.x * 1024 + tid;
    int v = (i < NNODES) ? g_deg[i] : 0;
    s[tid] = v;
    __syncthreads();
    for (int off = 1; off < 1024; off <<= 1) {
        int t = (tid >= off) ? s[tid - off] : 0;
        __syncthreads();
        s[tid] += t;
        __syncthreads();
    }
    if (i < NNODES) g_rowptr[i + 1] = s[tid];
    if (tid == 1023) g_bsum[blockIdx.x] = s[1023];
}

__global__ void scan2_kernel() {
    int acc = 0;
    for (int b = 0; b < 49; b++) { int t = g_bsum[b]; g_bsum[b] = acc; acc += t; }
}

__global__ void scan3_kernel() {
    int i = blockIdx.x * 1024 + threadIdx.x;
    if (i == 0) g_rowptr[0] = 0;
    if (i < NNODES) {
        int incl = g_rowptr[i + 1] + g_bsum[blockIdx.x];
        g_rowptr[i + 1] = incl;
        g_cur[i] = incl - g_deg[i];
        g_dis[i] = rsqrtf((float)(g_deg[i] + 1));
    }
}

__global__ void fill_csr_kernel(const int* __restrict__ src,
                                const int* __restrict__ dst) {
    for (int e = blockIdx.x * blockDim.x + threadIdx.x; e < NEDGES;
         e += gridDim.x * blockDim.x) {
        int d = dst[e];
        int p = atomicAdd(&g_cur[d], 1);
        g_colidx[p] = src[e];
    }
}

// ---------------- low-rank path ----------------
__global__ void zero_misc_kernel() {
    int i = blockIdx.x * blockDim.x + threadIdx.x;
    if (i < KLR * KLR) g_M[i] = 0.f;
    if (i < 2 * KLR)   g_cs[i] = 0.f;
    if (i < HD)        { g_mean[i] = 0.f; g_msq[i] = 0.f; }
}

__global__ void nf_kernel() {
    int lane = threadIdx.x;
    float s = 0.f;
    for (int k = lane; k < KLR; k += 32) s += g_cs[k] * g_cs[KLR + k];
#pragma unroll
    for (int o = 16; o > 0; o >>= 1) s += __shfl_down_sync(0xffffffffu, s, o);
    if (lane == 0) g_inv_nf = 1.0f / (s / (float)NNODES + 1e-6f);
}

// M = V^T @ Z (100x100): 200 k-split blocks, 7x7 register tile per thread.
__global__ void __launch_bounds__(256) vtz_kernel() {
    __shared__ float Vs[32][112];
    __shared__ float Zs[32][112];
    const int tid = threadIdx.x;
    const int i = tid >> 4;
    const int j = tid & 15;
    const int kbeg = blockIdx.x * 250;
    const int kend = min(kbeg + 250, NNODES);

    float acc[7][7];
#pragma unroll
    for (int p = 0; p < 7; p++)
#pragma unroll
        for (int q = 0; q < 7; q++) acc[p][q] = 0.f;

    for (int k0 = kbeg; k0 < kend; k0 += 32) {
        int km = kend - k0;
        for (int idx = tid; idx < 32 * 112; idx += 256) {
            int kk = idx / 112, cc = idx - kk * 112;
            float v = 0.f, z = 0.f;
            if (kk < km && cc < KLR) {
                size_t b = (size_t)(k0 + kk) * TD2;
                v = g_t[b + KLR + cc];
                z = g_t[b + 2 * KLR + cc];
            }
            Vs[kk][cc] = v;
            Zs[kk][cc] = z;
        }
        __syncthreads();
#pragma unroll 4
        for (int kk = 0; kk < 32; kk++) {
            float av[7], bz[7];
#pragma unroll
            for (int p = 0; p < 7; p++) av[p] = Vs[kk][i + 16 * p];
#pragma unroll
            for (int q = 0; q < 7; q++) bz[q] = Zs[kk][j + 16 * q];
#pragma unroll
            for (int p = 0; p < 7; p++)
#pragma unroll
                for (int q = 0; q < 7; q++)
                    acc[p][q] = fmaf(av[p], bz[q], acc[p][q]);
        }
        __syncthreads();
    }
#pragma unroll
    for (int p = 0; p < 7; p++) {
        int r = i + 16 * p;
        if (r >= KLR) break;
#pragma unroll
        for (int q = 0; q < 7; q++) {
            int c = j + 16 * q;
            if (c < KLR) atomicAdd(&g_M[r * KLR + c], acc[p][q]);
        }
    }
}

// packed combine cols 0..199 = [res/nf | T] as bf16 hi/lo
__global__ void __launch_bounds__(256) respack_kernel() {
    __shared__ float Msh[KLR * KLR];
    __shared__ float Ush[16 * KLR];
    int tid = threadIdx.x;
    int r0 = blockIdx.x * 16;
    for (int idx = tid; idx < KLR * KLR; idx += 256) Msh[idx] = g_M[idx];
    for (int idx = tid; idx < 16 * KLR; idx += 256) {
        int r = idx / KLR, c = idx % KLR;
        Ush[idx] = (r0 + r < NNODES) ? g_t[(size_t)(r0 + r) * TD2 + c] : 0.f;
    }
    __syncthreads();
    float inv = g_inv_nf;
    int r = tid >> 4;
    int cg = tid & 15;
    if (r0 + r < NNODES) {
        float acc[7];
#pragma unroll
        for (int q = 0; q < 7; q++) acc[q] = 0.f;
        for (int k = 0; k < KLR; k++) {
            float a = Ush[r * KLR + k];
#pragma unroll
            for (int q = 0; q < 7; q++) {
                int c = cg + q * 16;
                if (c < KLR) acc[q] = fmaf(a, Msh[k * KLR + c], acc[q]);
            }
        }
        size_t base = (size_t)(r0 + r) * GDC;
#pragma unroll
        for (int q = 0; q < 7; q++) {
            int c = cg + q * 16;
            if (c < KLR) {
                float v = acc[q] * inv;
                __nv_bfloat16 hi = __float2bfloat16(v);
                g_chi[base + c] = hi;
                g_clo[base + c] = __float2bfloat16(v - __bfloat162float(hi));
            }
        }
#pragma unroll
        for (int q = 0; q < 7; q++) {
            int c = cg + q * 16;
            if (c < KLR) {
                float v = g_t[(size_t)(r0 + r) * TD2 + 3 * KLR + c];
                __nv_bfloat16 hi = __float2bfloat16(v);
                g_chi[base + KLR + c] = hi;
                g_clo[base + KLR + c] = __float2bfloat16(v - __bfloat162float(hi));
            }
        }
    }
}

// cols 200..455 of combine input = relu(aggregate + cb) as bf16 hi/lo
__global__ void agg_kernel(const float* __restrict__ cb) {
    __shared__ int   sh_u[64];
    __shared__ float sh_w[64];
    const int v = blockIdx.x;
    const int c = threadIdx.x;
    const float dv = g_dis[v];
    float acc = g_h[(size_t)v * HD + c] * dv * dv;
    const int s0 = g_rowptr[v], e0 = g_rowptr[v + 1];
    for (int s = s0; s < e0; s += 64) {
        int m = min(64, e0 - s);
        __syncthreads();
        if (c < m) {
            int u = g_colidx[s + c];
            sh_u[c] = u;
            sh_w[c] = g_dis[u] * dv;
        }
        __syncthreads();
        int j = 0;
        for (; j + 4 <= m; j += 4) {
            float h0 = g_h[(size_t)sh_u[j + 0] * HD + c];
            float h1 = g_h[(size_t)sh_u[j + 1] * HD + c];
            float h2 = g_h[(size_t)sh_u[j + 2] * HD + c];
            float h3 = g_h[(size_t)sh_u[j + 3] * HD + c];
            acc = fmaf(h0, sh_w[j + 0], acc);
            acc = fmaf(h1, sh_w[j + 1], acc);
            acc = fmaf(h2, sh_w[j + 2], acc);
            acc = fmaf(h3, sh_w[j + 3], acc);
        }
        for (; j < m; j++)
            acc = fmaf(g_h[(size_t)sh_u[j] * HD + c], sh_w[j], acc);
    }
    acc = fmaxf(acc + cb[c], 0.f);
    __nv_bfloat16 hi = __float2bfloat16(acc);
    size_t o = (size_t)v * GDC + 200 + c;
    g_chi[o] = hi;
    g_clo[o] = __float2bfloat16(acc - __bfloat162float(hi));
}

// ---------------- BN apply: scale/shift computed inline ----------------
__global__ void bn_apply_kernel(const float* __restrict__ gam,
                                const float* __restrict__ bet) {
    size_t i = (size_t)blockIdx.x * blockDim.x + threadIdx.x;
    if (i < (size_t)NNODES * HD) {
        int c = (int)(i & (HD - 1));
        float m = g_mean[c] * (1.f / NNODES);
        float var = g_msq[c] * (1.f / NNODES) - m * m;
        float sc = __ldg(&gam[c]) * rsqrtf(var + 1e-5f);
        float sh = __ldg(&bet[c]) - m * sc;
        float v = fmaf(g_x[i], sc, sh);
        __nv_bfloat16 hi = __float2bfloat16(v);
        g_xhi[i] = hi;
        g_xlo[i] = __float2bfloat16(v - __bfloat162float(hi));
    }
}

// ---------------- host orchestration ----------------
extern "C" void kernel_launch(void* const* d_in, const int* in_sizes, int n_in,
                              void* d_out, int out_size) {
    (void)in_sizes; (void)n_in; (void)out_size;
    const float* x_in = (const float*)d_in[0];
    const int*   ei   = (const int*)d_in[1];
    const int*   src  = ei;
    const int*   dst  = ei + NEDGES;

    const float* cw[3] = {(const float*)d_in[2],  (const float*)d_in[8],  (const float*)d_in[14]};
    const float* cb[3] = {(const float*)d_in[3],  (const float*)d_in[9],  (const float*)d_in[15]};
    const float* aw[3] = {(const float*)d_in[4],  (const float*)d_in[10], (const float*)d_in[16]};
    const float* ab[3] = {(const float*)d_in[5],  (const float*)d_in[11], (const float*)d_in[17]};
    const float* rw[3] = {(const float*)d_in[6],  (const float*)d_in[12], (const float*)d_in[18]};
    const float* rb[3] = {(const float*)d_in[7],  (const float*)d_in[13], (const float*)d_in[19]};
    const float* gam[2] = {(const float*)d_in[20], (const float*)d_in[22]};
    const float* bet[2] = {(const float*)d_in[21], (const float*)d_in[23]};
    float* out = (float*)d_out;

    float *p_x, *p_h, *p_t;
    __nv_bfloat16 *p_xhi, *p_xlo, *p_chi, *p_clo, *p_wh, *p_wl;
    cudaGetSymbolAddress((void**)&p_x, g_x);
    cudaGetSymbolAddress((void**)&p_h, g_h);
    cudaGetSymbolAddress((void**)&p_t, g_t);
    cudaGetSymbolAddress((void**)&p_xhi, g_xhi);
    cudaGetSymbolAddress((void**)&p_xlo, g_xlo);
    cudaGetSymbolAddress((void**)&p_chi, g_chi);
    cudaGetSymbolAddress((void**)&p_clo, g_clo);
    cudaGetSymbolAddress((void**)&p_wh, g_wh);
    cudaGetSymbolAddress((void**)&p_wl, g_wl);

    const int SMB = 2 * STAGE_BYTES + 1024;

    static cudaStream_t s2 = nullptr, s3 = nullptr;
    static cudaEvent_t evFork = nullptr, evH = nullptr, evAgg = nullptr;
    static cudaEvent_t evW03 = nullptr, evW = nullptr;
    if (s2 == nullptr) {
        cudaFuncSetAttribute(mma_gemm, cudaFuncAttributeMaxDynamicSharedMemorySize, SMB);
        cudaFuncSetAttribute(mma_gemm_fused, cudaFuncAttributeMaxDynamicSharedMemorySize, SMB);
        cudaStreamCreateWithFlags(&s2, cudaStreamNonBlocking);
        cudaStreamCreateWithFlags(&s3, cudaStreamNonBlocking);
        cudaEventCreateWithFlags(&evFork, cudaEventDisableTiming);
        cudaEventCreateWithFlags(&evH, cudaEventDisableTiming);
        cudaEventCreateWithFlags(&evAgg, cudaEventDisableTiming);
        cudaEventCreateWithFlags(&evW03, cudaEventDisableTiming);
        cudaEventCreateWithFlags(&evW, cudaEventDisableTiming);
    }

    // ---- fork: CSR setup on s2, weight pre-split on s3 ----
    cudaEventRecord(evFork, 0);
    cudaStreamWaitEvent(s2, evFork, 0);
    cudaStreamWaitEvent(s3, evFork, 0);

    padzero_kernel<<<NNODES, 64, 0, s2>>>();
    zero_deg_kernel<<<(NNODES + 255) / 256, 256, 0, s2>>>();
    count_deg_kernel<<<800, 256, 0, s2>>>(dst);
    scan1_kernel<<<49, 1024, 0, s2>>>();
    scan2_kernel<<<1, 1, 0, s2>>>();
    scan3_kernel<<<49, 1024, 0, s2>>>();
    fill_csr_kernel<<<800, 256, 0, s2>>>(src, dst);

    const int dinv[3] = {128, 256, 256};
    for (int l = 0; l < 3; l++) {
        int K = dinv[l];
        int n1 = 256 * K;
        wsplit_kernel<<<(n1 + 255) / 256, 256, 0, s3>>>(cw[l], K, 256, 256, K, 3 * l, 0);
        int n2 = 448 * K;
        wsplit_kernel<<<(n2 + 255) / 256, 256, 0, s3>>>(aw[l], K, 400, 448, K, 3 * l, 256);
        int dout = (l < 2) ? 256 : 128;
        int n3 = dout * 512;
        wsplit_kernel<<<(n3 + 255) / 256, 256, 0, s3>>>(rw[l], 456, dout, dout, 512, 3 * l + 2, 0);
        if (l == 0) cudaEventRecord(evW03, s3);
    }
    cudaEventRecord(evW, s3);

    // ---- main stream: input conversion; wait only for layer-0 weights ----
    xsplit_kernel<<<(NNODES * 128 + 255) / 256, 256>>>(x_in, (long)NNODES * 128);
    cudaStreamWaitEvent(0, evW03, 0);

    for (int l = 0; l < 3; l++) {
        if (l == 1) cudaStreamWaitEvent(0, evW, 0);
        int din = dinv[l];
        const __nv_bfloat16* sh = p_wh + (size_t)(3 * l) * WSLOT;
        const __nv_bfloat16* sl = p_wl + (size_t)(3 * l) * WSLOT;
        const __nv_bfloat16* rwh = p_wh + (size_t)(3 * l + 2) * WSLOT;
        const __nv_bfloat16* rwl = p_wl + (size_t)(3 * l + 2) * WSLOT;

        // zero M/cs/mean/msq BEFORE fused GEMM (its epilogue writes g_cs)
        zero_misc_kernel<<<(KLR * KLR + 255) / 256, 256>>>();

        // fused: h = x@cw ; t = relu(x@aw + ab); colsum(g_cs) in epilogue
        mma_gemm_fused<<<dim3(11, MB), 256, SMB>>>(
            p_xhi, p_xlo, sh, sl, ab[l], p_h, p_t, NNODES, din);
        cudaEventRecord(evH, 0);

        // side stream: aggregation
        cudaStreamWaitEvent(s2, evH, 0);
        agg_kernel<<<NNODES, HD, 0, s2>>>(cb[l]);
        cudaEventRecord(evAgg, s2);

        // main: low-rank path (nf uses epilogue-computed g_cs)
        nf_kernel<<<1, 32>>>();
        vtz_kernel<<<200, 256>>>();
        respack_kernel<<<NNODES / 16, 256>>>();

        // join: combine needs agg output
        cudaStreamWaitEvent(0, evAgg, 0);
        if (l < 2) {
            mma_gemm<<<dim3(HD / 64, MB), 256, SMB>>>(
                p_chi, p_clo, rwh, rwl, rb[l], p_x, NNODES, GDC, HD, HD, 1, 1);
            bn_apply_kernel<<<(NNODES * HD + 255) / 256, 256>>>(gam[l], bet[l]);
        } else {
            mma_gemm<<<dim3(2, MB), 256, SMB>>>(
                p_chi, p_clo, rwh, rwl, rb[l], out, NNODES, GDC, 128, 128, 0, 0);
        }
    }
}

// round 12
// speedup vs baseline: 1.1923x; 1.1923x over previous
#include <cuda_runtime.h>
#include <cuda_bf16.h>
#include <cstdint>

// ---------------- problem constants ----------------
#define NNODES 50000
#define NEDGES 800000
#define HD     256
#define TD2    512
#define GDC    512
#define KLR    100
#define MB     391
#define WSLOT  (512 * 512)

// ---------------- static scratch ----------------
__device__ float g_x[NNODES * HD];
__device__ float g_h[NNODES * HD];
__device__ float g_t[NNODES * TD2];
__device__ __nv_bfloat16 g_xhi[NNODES * HD];
__device__ __nv_bfloat16 g_xlo[NNODES * HD];
__device__ __nv_bfloat16 g_chi[NNODES * GDC];
__device__ __nv_bfloat16 g_clo[NNODES * GDC];
__device__ __nv_bfloat16 g_wh[9 * WSLOT];
__device__ __nv_bfloat16 g_wl[9 * WSLOT];
__device__ float g_M[KLR * KLR];
__device__ float g_cs[2 * KLR];
__device__ float g_inv_nf;
__device__ float g_mean[HD];
__device__ float g_msq[HD];
__device__ float g_dis[NNODES];
__device__ int   g_deg[NNODES];
__device__ int   g_rowptr[NNODES + 1];
__device__ int   g_cur[NNODES];
__device__ int   g_colidx[NEDGES];
__device__ int   g_bsum[64];

// ---------------- PTX helpers ----------------
__device__ __forceinline__ uint32_t smem_u32(const void* p) {
    uint32_t a;
    asm("{ .reg .u64 t; cvta.to.shared.u64 t, %1; cvt.u32.u64 %0, t; }"
        : "=r"(a) : "l"(p));
    return a;
}

__device__ __forceinline__ void cp16(uint32_t dst, const void* src, int sz) {
    asm volatile("cp.async.cg.shared.global [%0], [%1], 16, %2;"
                 :: "r"(dst), "l"(src), "r"(sz) : "memory");
}

__device__ __forceinline__ void ldm_x4(uint32_t* r, uint32_t addr) {
    asm volatile("ldmatrix.sync.aligned.m8n8.x4.shared.b16 {%0,%1,%2,%3}, [%4];"
                 : "=r"(r[0]), "=r"(r[1]), "=r"(r[2]), "=r"(r[3]) : "r"(addr));
}

__device__ __forceinline__ void mma_bf16(float* d, const uint32_t* a,
                                         const uint32_t* b) {
    asm volatile(
        "mma.sync.aligned.m16n8k16.row.col.f32.bf16.bf16.f32 "
        "{%0,%1,%2,%3}, {%4,%5,%6,%7}, {%8,%9}, {%0,%1,%2,%3};"
        : "+f"(d[0]), "+f"(d[1]), "+f"(d[2]), "+f"(d[3])
        : "r"(a[0]), "r"(a[1]), "r"(a[2]), "r"(a[3]), "r"(b[0]), "r"(b[1]));
}

// ---------------- shared GEMM mainloop (round-6 proven config) ----------------
#define STAGE_BYTES 49152

#define GEMM_MAINLOOP(ACC)                                                     \
    extern __shared__ char dsm_raw[];                                          \
    uint32_t base0 = (smem_u32(dsm_raw) + 1023u) & ~1023u;                     \
    const int tid = threadIdx.x;                                               \
    const int wid = tid >> 5;                                                  \
    const int lane = tid & 31;                                                 \
    const int wm = wid & 3;                                                    \
    const int wn = wid >> 2;                                                   \
    const int row0 = blockIdx.y * 128;                                         \
    const int col0 = blockIdx.x * 64;                                          \
    const __nv_bfloat16* Bh0 = Bh + (size_t)col0 * K;                          \
    const __nv_bfloat16* Bl0 = Bl + (size_t)col0 * K;                          \
    const int nc = K >> 6;                                                     \
    float ACC[2][4][4];                                                        \
    _Pragma("unroll")                                                          \
    for (int mt = 0; mt < 2; mt++)                                             \
        _Pragma("unroll")                                                      \
        for (int nt = 0; nt < 4; nt++)                                         \
            _Pragma("unroll")                                                  \
            for (int q = 0; q < 4; q++) ACC[mt][nt][q] = 0.f;                  \
    auto load_chunk = [&](int c) {                                             \
        uint32_t sb = base0 + (uint32_t)(c & 1) * STAGE_BYTES;                 \
        int k0 = c << 6;                                                       \
        _Pragma("unroll 4")                                                    \
        for (int j = 0; j < 4; j++) {                                          \
            int i = tid + j * 256;                                             \
            int r = i >> 3, seg = i & 7;                                       \
            int off = r * 128 + seg * 16;                                      \
            uint32_t sw = (uint32_t)(off ^ ((off >> 3) & 0x70));               \
            int ga = row0 + r;                                                 \
            int ok = (ga < M) ? 16 : 0;                                        \
            if (ga >= M) ga = 0;                                               \
            size_t ao = (size_t)ga * K + k0 + seg * 8;                         \
            cp16(sb + sw,         Ah + ao, ok);                                \
            cp16(sb + 16384 + sw, Al + ao, ok);                                \
        }                                                                      \
        {                                                                      \
            int i = tid;                                                       \
            int r = i >> 3, seg = i & 7;                                       \
            int off = r * 128 + seg * 16;                                      \
            uint32_t sw = (uint32_t)(off ^ ((off >> 3) & 0x70));               \
            size_t bo = (size_t)r * K + k0 + seg * 8;                          \
            cp16(sb + 32768 + sw, Bh0 + bo, 16);                               \
            cp16(sb + 40960 + sw, Bl0 + bo, 16);                               \
        }                                                                      \
        {                                                                      \
            int i = tid + 256;                                                 \
            int r = i >> 3, seg = i & 7;                                       \
            int off = r * 128 + seg * 16;                                      \
            uint32_t sw = (uint32_t)(off ^ ((off >> 3) & 0x70));               \
            size_t bo = (size_t)r * K + k0 + seg * 8;                          \
            cp16(sb + 32768 + sw, Bh0 + bo, 16);                               \
            cp16(sb + 40960 + sw, Bl0 + bo, 16);                               \
        }                                                                      \
        asm volatile("cp.async.commit_group;" ::: "memory");                   \
    };                                                                         \
    const int a_off0 = (wm * 32 + (lane & 15)) * 128 + ((lane >> 4) << 4);     \
    const int b_off0 = (wn * 32 + ((lane >> 4) << 3) + (lane & 7)) * 128       \
                     + (((lane >> 3) & 1) << 4);                               \
    load_chunk(0);                                                             \
    for (int c = 0; c < nc; c++) {                                             \
        if (c + 1 < nc) {                                                      \
            load_chunk(c + 1);                                                 \
            asm volatile("cp.async.wait_group 1;" ::: "memory");               \
        } else {                                                               \
            asm volatile("cp.async.wait_group 0;" ::: "memory");               \
        }                                                                      \
        __syncthreads();                                                       \
        uint32_t sb = base0 + (uint32_t)(c & 1) * STAGE_BYTES;                 \
        _Pragma("unroll")                                                      \
        for (int kk = 0; kk < 4; kk++) {                                       \
            uint32_t ah[2][4], al[2][4], bh[2][4], bl[2][4];                   \
            _Pragma("unroll")                                                  \
            for (int mt = 0; mt < 2; mt++) {                                   \
                int off = a_off0 + mt * 2048 + kk * 32;                        \
                uint32_t sw = (uint32_t)(off ^ ((off >> 3) & 0x70));           \
                ldm_x4(ah[mt], sb + sw);                                       \
                ldm_x4(al[mt], sb + 16384 + sw);                               \
            }                                                                  \
            _Pragma("unroll")                                                  \
            for (int np = 0; np < 2; np++) {                                   \
                int off = b_off0 + np * 2048 + kk * 32;                        \
                uint32_t sw = (uint32_t)(off ^ ((off >> 3) & 0x70));           \
                ldm_x4(bh[np], sb + 32768 + sw);                               \
                ldm_x4(bl[np], sb + 40960 + sw);                               \
            }                                                                  \
            _Pragma("unroll")                                                  \
            for (int mt = 0; mt < 2; mt++)                                     \
                _Pragma("unroll")                                              \
                for (int nt = 0; nt < 4; nt++) {                               \
                    const uint32_t* bhp = &bh[nt >> 1][(nt & 1) * 2];          \
                    const uint32_t* blp = &bl[nt >> 1][(nt & 1) * 2];          \
                    mma_bf16(ACC[mt][nt], ah[mt], bhp);                        \
                    mma_bf16(ACC[mt][nt], ah[mt], blp);                        \
                    mma_bf16(ACC[mt][nt], al[mt], bhp);                        \
                }                                                              \
        }                                                                      \
        __syncthreads();                                                       \
    }

// ---------------- plain GEMM: C = act(A@B^T + bias) ----------------
__global__ void __launch_bounds__(256, 2)
mma_gemm(const __nv_bfloat16* __restrict__ Ah, const __nv_bfloat16* __restrict__ Al,
         const __nv_bfloat16* __restrict__ Bh, const __nv_bfloat16* __restrict__ Bl,
         const float* __restrict__ bias, float* __restrict__ C,
         int M, int K, int ldc, int nvalid, int relu) {
    GEMM_MAINLOOP(acc)
#pragma unroll
    for (int mt = 0; mt < 2; mt++) {
        int ra = row0 + wm * 32 + mt * 16 + (lane >> 2);
        int rb = ra + 8;
#pragma unroll
        for (int nt = 0; nt < 4; nt++) {
            int c0 = col0 + wn * 32 + nt * 8 + (lane & 3) * 2;
            float bv0 = 0.f, bv1 = 0.f;
            if (bias && c0 < nvalid) {
                bv0 = __ldg(&bias[c0]);
                bv1 = __ldg(&bias[c0 + 1]);
            }
            float v0 = acc[mt][nt][0] + bv0;
            float v1 = acc[mt][nt][1] + bv1;
            float v2 = acc[mt][nt][2] + bv0;
            float v3 = acc[mt][nt][3] + bv1;
            if (relu) {
                v0 = fmaxf(v0, 0.f); v1 = fmaxf(v1, 0.f);
                v2 = fmaxf(v2, 0.f); v3 = fmaxf(v3, 0.f);
            }
            if (ra < M) *(float2*)&C[(size_t)ra * ldc + c0] = make_float2(v0, v1);
            if (rb < M) *(float2*)&C[(size_t)rb * ldc + c0] = make_float2(v2, v3);
        }
    }
}

// ---------------- fused h+t GEMM ----------------
__global__ void __launch_bounds__(256, 2)
mma_gemm_fused(const __nv_bfloat16* __restrict__ Ah, const __nv_bfloat16* __restrict__ Al,
               const __nv_bfloat16* __restrict__ Bh, const __nv_bfloat16* __restrict__ Bl,
               const float* __restrict__ bias2,
               float* __restrict__ C1, float* __restrict__ C2,
               int M, int K) {
    GEMM_MAINLOOP(acc)
    float* C;
    int ldc, rel, cbase, nval;
    const float* bias;
    if (col0 < 256) {
        C = C1; ldc = HD; rel = 0; bias = nullptr; cbase = col0; nval = HD;
    } else {
        C = C2; ldc = TD2; rel = 1; bias = bias2; cbase = col0 - 256; nval = 400;
    }
#pragma unroll
    for (int mt = 0; mt < 2; mt++) {
        int ra = row0 + wm * 32 + mt * 16 + (lane >> 2);
        int rb = ra + 8;
#pragma unroll
        for (int nt = 0; nt < 4; nt++) {
            int c0 = cbase + wn * 32 + nt * 8 + (lane & 3) * 2;
            float bv0 = 0.f, bv1 = 0.f;
            if (bias && c0 < nval) {
                bv0 = __ldg(&bias[c0]);
                bv1 = __ldg(&bias[c0 + 1]);
            }
            float v0 = acc[mt][nt][0] + bv0;
            float v1 = acc[mt][nt][1] + bv1;
            float v2 = acc[mt][nt][2] + bv0;
            float v3 = acc[mt][nt][3] + bv1;
            if (rel) {
                v0 = fmaxf(v0, 0.f); v1 = fmaxf(v1, 0.f);
                v2 = fmaxf(v2, 0.f); v3 = fmaxf(v3, 0.f);
            }
            if (ra < M) *(float2*)&C[(size_t)ra * ldc + c0] = make_float2(v0, v1);
            if (rb < M) *(float2*)&C[(size_t)rb * ldc + c0] = make_float2(v2, v3);
        }
    }
}

// ---------------- conversion kernels ----------------
__global__ void xsplit_kernel(const float* __restrict__ x, long n) {
    long i = (long)blockIdx.x * blockDim.x + threadIdx.x;
    if (i < n) {
        float v = x[i];
        __nv_bfloat16 hi = __float2bfloat16(v);
        g_xhi[i] = hi;
        g_xlo[i] = __float2bfloat16(v - __bfloat162float(hi));
    }
}

__global__ void wsplit_kernel(const float* __restrict__ W, int K, int N,
                              int Nout, int Kpad, int slot, int row0) {
    int i = blockIdx.x * blockDim.x + threadIdx.x;
    if (i < Nout * Kpad) {
        int n = i / Kpad, k = i - n * Kpad;
        float v = (n < N && k < K) ? W[(size_t)k * N + n] : 0.f;
        __nv_bfloat16 hi = __float2bfloat16(v);
        size_t o = (size_t)slot * WSLOT + (size_t)(row0 + n) * Kpad + k;
        g_wh[o] = hi;
        g_wl[o] = __float2bfloat16(v - __bfloat162float(hi));
    }
}

__global__ void padzero_kernel() {
    int v = blockIdx.x, c = threadIdx.x;
    if (c < GDC - 456) {
        size_t o = (size_t)v * GDC + 456 + c;
        g_chi[o] = __float2bfloat16(0.f);
        g_clo[o] = __float2bfloat16(0.f);
    }
}

// ---------------- graph setup ----------------
__global__ void zero_deg_kernel() {
    int i = blockIdx.x * blockDim.x + threadIdx.x;
    if (i < NNODES) g_deg[i] = 0;
}

__global__ void count_deg_kernel(const int* __restrict__ dst) {
    for (int e = blockIdx.x * blockDim.x + threadIdx.x; e < NEDGES;
         e += gridDim.x * blockDim.x)
        atomicAdd(&g_deg[dst[e]], 1);
}

__global__ void scan1_kernel() {
    __shared__ int s[1024];
    int tid = threadIdx.x;
    int i = blockIdx.x * 1024 + tid;
    int v = (i < NNODES) ? g_deg[i] : 0;
    s[tid] = v;
    __syncthreads();
    for (int off = 1; off < 1024; off <<= 1) {
        int t = (tid >= off) ? s[tid - off] : 0;
        __syncthreads();
        s[tid] += t;
        __syncthreads();
    }
    if (i < NNODES) g_rowptr[i + 1] = s[tid];
    if (tid == 1023) g_bsum[blockIdx.x] = s[1023];
}

__global__ void scan2_kernel() {
    int acc = 0;
    for (int b = 0; b < 49; b++) { int t = g_bsum[b]; g_bsum[b] = acc; acc += t; }
}

__global__ void scan3_kernel() {
    int i = blockIdx.x * 1024 + threadIdx.x;
    if (i == 0) g_rowptr[0] = 0;
    if (i < NNODES) {
        int incl = g_rowptr[i + 1] + g_bsum[blockIdx.x];
        g_rowptr[i + 1] = incl;
        g_cur[i] = incl - g_deg[i];
        g_dis[i] = rsqrtf((float)(g_deg[i] + 1));
    }
}

__global__ void fill_csr_kernel(const int* __restrict__ src,
                                const int* __restrict__ dst) {
    for (int e = blockIdx.x * blockDim.x + threadIdx.x; e < NEDGES;
         e += gridDim.x * blockDim.x) {
        int d = dst[e];
        int p = atomicAdd(&g_cur[d], 1);
        g_colidx[p] = src[e];
    }
}

// ---------------- low-rank path ----------------
__global__ void zero_misc_kernel() {
    int i = blockIdx.x * blockDim.x + threadIdx.x;
    if (i < KLR * KLR) g_M[i] = 0.f;
    if (i < 2 * KLR)   g_cs[i] = 0.f;
    if (i < HD)        { g_mean[i] = 0.f; g_msq[i] = 0.f; }
}

__global__ void colsum_kernel() {
    int col = threadIdx.x;
    int r0 = blockIdx.x * 256;
    if (col < 2 * KLR) {
        float s = 0.f;
        int rend = min(r0 + 256, NNODES);
        for (int r = r0; r < rend; r++) s += g_t[(size_t)r * TD2 + col];
        atomicAdd(&g_cs[col], s);
    }
}

__global__ void nf_kernel() {
    int lane = threadIdx.x;
    float s = 0.f;
    for (int k = lane; k < KLR; k += 32) s += g_cs[k] * g_cs[KLR + k];
#pragma unroll
    for (int o = 16; o > 0; o >>= 1) s += __shfl_down_sync(0xffffffffu, s, o);
    if (lane == 0) g_inv_nf = 1.0f / (s / (float)NNODES + 1e-6f);
}

// M = V^T @ Z (100x100): 200 k-split blocks, 7x7 register tile per thread.
__global__ void __launch_bounds__(256) vtz_kernel() {
    __shared__ float Vs[32][112];
    __shared__ float Zs[32][112];
    const int tid = threadIdx.x;
    const int i = tid >> 4;
    const int j = tid & 15;
    const int kbeg = blockIdx.x * 250;
    const int kend = min(kbeg + 250, NNODES);

    float acc[7][7];
#pragma unroll
    for (int p = 0; p < 7; p++)
#pragma unroll
        for (int q = 0; q < 7; q++) acc[p][q] = 0.f;

    for (int k0 = kbeg; k0 < kend; k0 += 32) {
        int km = kend - k0;
        for (int idx = tid; idx < 32 * 112; idx += 256) {
            int kk = idx / 112, cc = idx - kk * 112;
            float v = 0.f, z = 0.f;
            if (kk < km && cc < KLR) {
                size_t b = (size_t)(k0 + kk) * TD2;
                v = g_t[b + KLR + cc];
                z = g_t[b + 2 * KLR + cc];
            }
            Vs[kk][cc] = v;
            Zs[kk][cc] = z;
        }
        __syncthreads();
#pragma unroll 4
        for (int kk = 0; kk < 32; kk++) {
            float av[7], bz[7];
#pragma unroll
            for (int p = 0; p < 7; p++) av[p] = Vs[kk][i + 16 * p];
#pragma unroll
            for (int q = 0; q < 7; q++) bz[q] = Zs[kk][j + 16 * q];
#pragma unroll
            for (int p = 0; p < 7; p++)
#pragma unroll
                for (int q = 0; q < 7; q++)
                    acc[p][q] = fmaf(av[p], bz[q], acc[p][q]);
        }
        __syncthreads();
    }
#pragma unroll
    for (int p = 0; p < 7; p++) {
        int r = i + 16 * p;
        if (r >= KLR) break;
#pragma unroll
        for (int q = 0; q < 7; q++) {
            int c = j + 16 * q;
            if (c < KLR) atomicAdd(&g_M[r * KLR + c], acc[p][q]);
        }
    }
}

// packed combine cols 0..199 = [res/nf | T] as bf16 hi/lo
__global__ void __launch_bounds__(256) respack_kernel() {
    __shared__ float Msh[KLR * KLR];
    __shared__ float Ush[16 * KLR];
    int tid = threadIdx.x;
    int r0 = blockIdx.x * 16;
    for (int idx = tid; idx < KLR * KLR; idx += 256) Msh[idx] = g_M[idx];
    for (int idx = tid; idx < 16 * KLR; idx += 256) {
        int r = idx / KLR, c = idx % KLR;
        Ush[idx] = (r0 + r < NNODES) ? g_t[(size_t)(r0 + r) * TD2 + c] : 0.f;
    }
    __syncthreads();
    float inv = g_inv_nf;
    int r = tid >> 4;
    int cg = tid & 15;
    if (r0 + r < NNODES) {
        float acc[7];
#pragma unroll
        for (int q = 0; q < 7; q++) acc[q] = 0.f;
        for (int k = 0; k < KLR; k++) {
            float a = Ush[r * KLR + k];
#pragma unroll
            for (int q = 0; q < 7; q++) {
                int c = cg + q * 16;
                if (c < KLR) acc[q] = fmaf(a, Msh[k * KLR + c], acc[q]);
            }
        }
        size_t base = (size_t)(r0 + r) * GDC;
#pragma unroll
        for (int q = 0; q < 7; q++) {
            int c = cg + q * 16;
            if (c < KLR) {
                float v = acc[q] * inv;
                __nv_bfloat16 hi = __float2bfloat16(v);
                g_chi[base + c] = hi;
                g_clo[base + c] = __float2bfloat16(v - __bfloat162float(hi));
            }
        }
#pragma unroll
        for (int q = 0; q < 7; q++) {
            int c = cg + q * 16;
            if (c < KLR) {
                float v = g_t[(size_t)(r0 + r) * TD2 + 3 * KLR + c];
                __nv_bfloat16 hi = __float2bfloat16(v);
                g_chi[base + KLR + c] = hi;
                g_clo[base + KLR + c] = __float2bfloat16(v - __bfloat162float(hi));
            }
        }
    }
}

// cols 200..455 of combine input = relu(aggregate + cb) as bf16 hi/lo
__global__ void agg_kernel(const float* __restrict__ cb) {
    __shared__ int   sh_u[64];
    __shared__ float sh_w[64];
    const int v = blockIdx.x;
    const int c = threadIdx.x;
    const float dv = g_dis[v];
    float acc = g_h[(size_t)v * HD + c] * dv * dv;
    const int s0 = g_rowptr[v], e0 = g_rowptr[v + 1];
    for (int s = s0; s < e0; s += 64) {
        int m = min(64, e0 - s);
        __syncthreads();
        if (c < m) {
            int u = g_colidx[s + c];
            sh_u[c] = u;
            sh_w[c] = g_dis[u] * dv;
        }
        __syncthreads();
        int j = 0;
        for (; j + 4 <= m; j += 4) {
            float h0 = g_h[(size_t)sh_u[j + 0] * HD + c];
            float h1 = g_h[(size_t)sh_u[j + 1] * HD + c];
            float h2 = g_h[(size_t)sh_u[j + 2] * HD + c];
            float h3 = g_h[(size_t)sh_u[j + 3] * HD + c];
            acc = fmaf(h0, sh_w[j + 0], acc);
            acc = fmaf(h1, sh_w[j + 1], acc);
            acc = fmaf(h2, sh_w[j + 2], acc);
            acc = fmaf(h3, sh_w[j + 3], acc);
        }
        for (; j < m; j++)
            acc = fmaf(g_h[(size_t)sh_u[j] * HD + c], sh_w[j], acc);
    }
    acc = fmaxf(acc + cb[c], 0.f);
    __nv_bfloat16 hi = __float2bfloat16(acc);
    size_t o = (size_t)v * GDC + 200 + c;
    g_chi[o] = hi;
    g_clo[o] = __float2bfloat16(acc - __bfloat162float(hi));
}

// ---------------- batch norm ----------------
__global__ void bn_stats_kernel() {
    int col = threadIdx.x;
    int r0 = blockIdx.x * 128;
    int rend = min(r0 + 128, NNODES);
    float s = 0.f, s2 = 0.f;
    for (int r = r0; r < rend; r++) {
        float v = g_x[(size_t)r * HD + col];
        s += v;
        s2 = fmaf(v, v, s2);
    }
    atomicAdd(&g_mean[col], s);
    atomicAdd(&g_msq[col], s2);
}

// scale/shift computed inline from raw sums (bn_final eliminated)
__global__ void bn_apply_kernel(const float* __restrict__ gam,
                                const float* __restrict__ bet) {
    size_t i = (size_t)blockIdx.x * blockDim.x + threadIdx.x;
    if (i < (size_t)NNODES * HD) {
        int c = (int)(i & (HD - 1));
        float m = g_mean[c] * (1.f / NNODES);
        float var = g_msq[c] * (1.f / NNODES) - m * m;
        float sc = __ldg(&gam[c]) * rsqrtf(var + 1e-5f);
        float sh = __ldg(&bet[c]) - m * sc;
        float v = fmaf(g_x[i], sc, sh);
        __nv_bfloat16 hi = __float2bfloat16(v);
        g_xhi[i] = hi;
        g_xlo[i] = __float2bfloat16(v - __bfloat162float(hi));
    }
}

// ---------------- host orchestration ----------------
extern "C" void kernel_launch(void* const* d_in, const int* in_sizes, int n_in,
                              void* d_out, int out_size) {
    (void)in_sizes; (void)n_in; (void)out_size;
    const float* x_in = (const float*)d_in[0];
    const int*   ei   = (const int*)d_in[1];
    const int*   src  = ei;
    const int*   dst  = ei + NEDGES;

    const float* cw[3] = {(const float*)d_in[2],  (const float*)d_in[8],  (const float*)d_in[14]};
    const float* cb[3] = {(const float*)d_in[3],  (const float*)d_in[9],  (const float*)d_in[15]};
    const float* aw[3] = {(const float*)d_in[4],  (const float*)d_in[10], (const float*)d_in[16]};
    const float* ab[3] = {(const float*)d_in[5],  (const float*)d_in[11], (const float*)d_in[17]};
    const float* rw[3] = {(const float*)d_in[6],  (const float*)d_in[12], (const float*)d_in[18]};
    const float* rb[3] = {(const float*)d_in[7],  (const float*)d_in[13], (const float*)d_in[19]};
    const float* gam[2] = {(const float*)d_in[20], (const float*)d_in[22]};
    const float* bet[2] = {(const float*)d_in[21], (const float*)d_in[23]};
    float* out = (float*)d_out;

    float *p_x, *p_h, *p_t;
    __nv_bfloat16 *p_xhi, *p_xlo, *p_chi, *p_clo, *p_wh, *p_wl;
    cudaGetSymbolAddress((void**)&p_x, g_x);
    cudaGetSymbolAddress((void**)&p_h, g_h);
    cudaGetSymbolAddress((void**)&p_t, g_t);
    cudaGetSymbolAddress((void**)&p_xhi, g_xhi);
    cudaGetSymbolAddress((void**)&p_xlo, g_xlo);
    cudaGetSymbolAddress((void**)&p_chi, g_chi);
    cudaGetSymbolAddress((void**)&p_clo, g_clo);
    cudaGetSymbolAddress((void**)&p_wh, g_wh);
    cudaGetSymbolAddress((void**)&p_wl, g_wl);

    const int SMB = 2 * STAGE_BYTES + 1024;

    static cudaStream_t s2 = nullptr, s3 = nullptr;
    static cudaEvent_t evFork = nullptr, evH = nullptr, evAgg = nullptr;
    static cudaEvent_t evW03 = nullptr, evW = nullptr;
    if (s2 == nullptr) {
        cudaFuncSetAttribute(mma_gemm, cudaFuncAttributeMaxDynamicSharedMemorySize, SMB);
        cudaFuncSetAttribute(mma_gemm_fused, cudaFuncAttributeMaxDynamicSharedMemorySize, SMB);
        cudaStreamCreateWithFlags(&s2, cudaStreamNonBlocking);
        cudaStreamCreateWithFlags(&s3, cudaStreamNonBlocking);
        cudaEventCreateWithFlags(&evFork, cudaEventDisableTiming);
        cudaEventCreateWithFlags(&evH, cudaEventDisableTiming);
        cudaEventCreateWithFlags(&evAgg, cudaEventDisableTiming);
        cudaEventCreateWithFlags(&evW03, cudaEventDisableTiming);
        cudaEventCreateWithFlags(&evW, cudaEventDisableTiming);
    }

    // ---- fork: CSR setup on s2, weight pre-split on s3 ----
    cudaEventRecord(evFork, 0);
    cudaStreamWaitEvent(s2, evFork, 0);
    cudaStreamWaitEvent(s3, evFork, 0);

    padzero_kernel<<<NNODES, 64, 0, s2>>>();
    zero_deg_kernel<<<(NNODES + 255) / 256, 256, 0, s2>>>();
    count_deg_kernel<<<800, 256, 0, s2>>>(dst);
    scan1_kernel<<<49, 1024, 0, s2>>>();
    scan2_kernel<<<1, 1, 0, s2>>>();
    scan3_kernel<<<49, 1024, 0, s2>>>();
    fill_csr_kernel<<<800, 256, 0, s2>>>(src, dst);

    const int dinv[3] = {128, 256, 256};
    for (int l = 0; l < 3; l++) {
        int K = dinv[l];
        int n1 = 256 * K;
        wsplit_kernel<<<(n1 + 255) / 256, 256, 0, s3>>>(cw[l], K, 256, 256, K, 3 * l, 0);
        int n2 = 448 * K;
        wsplit_kernel<<<(n2 + 255) / 256, 256, 0, s3>>>(aw[l], K, 400, 448, K, 3 * l, 256);
        int dout = (l < 2) ? 256 : 128;
        int n3 = dout * 512;
        wsplit_kernel<<<(n3 + 255) / 256, 256, 0, s3>>>(rw[l], 456, dout, dout, 512, 3 * l + 2, 0);
        if (l == 0) cudaEventRecord(evW03, s3);
    }
    cudaEventRecord(evW, s3);

    // ---- main stream: input conversion; wait only for layer-0 weights ----
    xsplit_kernel<<<(NNODES * 128 + 255) / 256, 256>>>(x_in, (long)NNODES * 128);
    cudaStreamWaitEvent(0, evW03, 0);

    for (int l = 0; l < 3; l++) {
        if (l == 1) cudaStreamWaitEvent(0, evW, 0);
        int din = dinv[l];
        const __nv_bfloat16* sh = p_wh + (size_t)(3 * l) * WSLOT;
        const __nv_bfloat16* sl = p_wl + (size_t)(3 * l) * WSLOT;
        const __nv_bfloat16* rwh = p_wh + (size_t)(3 * l + 2) * WSLOT;
        const __nv_bfloat16* rwl = p_wl + (size_t)(3 * l + 2) * WSLOT;

        // fused: h = x@cw ; t = relu(x@aw + ab)  (11 column tiles)
        mma_gemm_fused<<<dim3(11, MB), 256, SMB>>>(
            p_xhi, p_xlo, sh, sl, ab[l], p_h, p_t, NNODES, din);
        cudaEventRecord(evH, 0);

        // side stream: aggregation
        cudaStreamWaitEvent(s2, evH, 0);
        agg_kernel<<<NNODES, HD, 0, s2>>>(cb[l]);
        cudaEventRecord(evAgg, s2);

        // main: low-rank path
        zero_misc_kernel<<<(KLR * KLR + 255) / 256, 256>>>();
        colsum_kernel<<<(NNODES + 255) / 256, 256>>>();
        nf_kernel<<<1, 32>>>();
        vtz_kernel<<<200, 256>>>();
        respack_kernel<<<NNODES / 16, 256>>>();

        // join: combine needs agg output
        cudaStreamWaitEvent(0, evAgg, 0);
        if (l < 2) {
            mma_gemm<<<dim3(HD / 64, MB), 256, SMB>>>(
                p_chi, p_clo, rwh, rwl, rb[l], p_x, NNODES, GDC, HD, HD, 1);
            bn_stats_kernel<<<(NNODES + 127) / 128, 256>>>();
            bn_apply_kernel<<<(NNODES * HD + 255) / 256, 256>>>(gam[l], bet[l]);
        } else {
            mma_gemm<<<dim3(2, MB), 256, SMB>>>(
                p_chi, p_clo, rwh, rwl, rb[l], out, NNODES, GDC, 128, 128, 0);
        }
    }
}

// round 13
// speedup vs baseline: 1.2366x; 1.0372x over previous
#include <cuda_runtime.h>
#include <cuda_bf16.h>
#include <cstdint>

// ---------------- problem constants ----------------
#define NNODES 50000
#define NEDGES 800000
#define HD     256
#define TD2    512
#define GDC    512
#define KLR    100
#define MB     391
#define WSLOT  (512 * 512)

// ---------------- static scratch ----------------
__device__ float g_x[NNODES * HD];
__device__ float g_h[NNODES * HD];
__device__ float g_t[NNODES * TD2];
__device__ __nv_bfloat16 g_xhi[NNODES * HD];
__device__ __nv_bfloat16 g_xlo[NNODES * HD];
__device__ __nv_bfloat16 g_chi[NNODES * GDC];
__device__ __nv_bfloat16 g_clo[NNODES * GDC];
__device__ __nv_bfloat16 g_wh[9 * WSLOT];
__device__ __nv_bfloat16 g_wl[9 * WSLOT];
__device__ float g_M[KLR * KLR];
__device__ float g_cs[2 * KLR];
__device__ float g_inv_nf;
__device__ float g_mean[HD];
__device__ float g_msq[HD];
__device__ float g_dis[NNODES];
__device__ int   g_deg[NNODES];
__device__ int   g_rowptr[NNODES + 1];
__device__ int   g_cur[NNODES];
__device__ int   g_colidx[NEDGES];
__device__ int   g_bsum[64];

// ---------------- PTX helpers ----------------
__device__ __forceinline__ uint32_t smem_u32(const void* p) {
    uint32_t a;
    asm("{ .reg .u64 t; cvta.to.shared.u64 t, %1; cvt.u32.u64 %0, t; }"
        : "=r"(a) : "l"(p));
    return a;
}

__device__ __forceinline__ void cp16(uint32_t dst, const void* src, int sz) {
    asm volatile("cp.async.cg.shared.global [%0], [%1], 16, %2;"
                 :: "r"(dst), "l"(src), "r"(sz) : "memory");
}

__device__ __forceinline__ void ldm_x4(uint32_t* r, uint32_t addr) {
    asm volatile("ldmatrix.sync.aligned.m8n8.x4.shared.b16 {%0,%1,%2,%3}, [%4];"
                 : "=r"(r[0]), "=r"(r[1]), "=r"(r[2]), "=r"(r[3]) : "r"(addr));
}

__device__ __forceinline__ void mma_bf16(float* d, const uint32_t* a,
                                         const uint32_t* b) {
    asm volatile(
        "mma.sync.aligned.m16n8k16.row.col.f32.bf16.bf16.f32 "
        "{%0,%1,%2,%3}, {%4,%5,%6,%7}, {%8,%9}, {%0,%1,%2,%3};"
        : "+f"(d[0]), "+f"(d[1]), "+f"(d[2]), "+f"(d[3])
        : "r"(a[0]), "r"(a[1]), "r"(a[2]), "r"(a[3]), "r"(b[0]), "r"(b[1]));
}

// ---------------- shared GEMM mainloop (round-6 proven config) ----------------
#define STAGE_BYTES 49152

#define GEMM_MAINLOOP(ACC)                                                     \
    extern __shared__ char dsm_raw[];                                          \
    uint32_t base0 = (smem_u32(dsm_raw) + 1023u) & ~1023u;                     \
    const int tid = threadIdx.x;                                               \
    const int wid = tid >> 5;                                                  \
    const int lane = tid & 31;                                                 \
    const int wm = wid & 3;                                                    \
    const int wn = wid >> 2;                                                   \
    const int row0 = blockIdx.y * 128;                                         \
    const int col0 = blockIdx.x * 64;                                          \
    const __nv_bfloat16* Bh0 = Bh + (size_t)col0 * K;                          \
    const __nv_bfloat16* Bl0 = Bl + (size_t)col0 * K;                          \
    const int nc = K >> 6;                                                     \
    float ACC[2][4][4];                                                        \
    _Pragma("unroll")                                                          \
    for (int mt = 0; mt < 2; mt++)                                             \
        _Pragma("unroll")                                                      \
        for (int nt = 0; nt < 4; nt++)                                         \
            _Pragma("unroll")                                                  \
            for (int q = 0; q < 4; q++) ACC[mt][nt][q] = 0.f;                  \
    auto load_chunk = [&](int c) {                                             \
        uint32_t sb = base0 + (uint32_t)(c & 1) * STAGE_BYTES;                 \
        int k0 = c << 6;                                                       \
        _Pragma("unroll 4")                                                    \
        for (int j = 0; j < 4; j++) {                                          \
            int i = tid + j * 256;                                             \
            int r = i >> 3, seg = i & 7;                                       \
            int off = r * 128 + seg * 16;                                      \
            uint32_t sw = (uint32_t)(off ^ ((off >> 3) & 0x70));               \
            int ga = row0 + r;                                                 \
            int ok = (ga < M) ? 16 : 0;                                        \
            if (ga >= M) ga = 0;                                               \
            size_t ao = (size_t)ga * K + k0 + seg * 8;                         \
            cp16(sb + sw,         Ah + ao, ok);                                \
            cp16(sb + 16384 + sw, Al + ao, ok);                                \
        }                                                                      \
        {                                                                      \
            int i = tid;                                                       \
            int r = i >> 3, seg = i & 7;                                       \
            int off = r * 128 + seg * 16;                                      \
            uint32_t sw = (uint32_t)(off ^ ((off >> 3) & 0x70));               \
            size_t bo = (size_t)r * K + k0 + seg * 8;                          \
            cp16(sb + 32768 + sw, Bh0 + bo, 16);                               \
            cp16(sb + 40960 + sw, Bl0 + bo, 16);                               \
        }                                                                      \
        {                                                                      \
            int i = tid + 256;                                                 \
            int r = i >> 3, seg = i & 7;                                       \
            int off = r * 128 + seg * 16;                                      \
            uint32_t sw = (uint32_t)(off ^ ((off >> 3) & 0x70));               \
            size_t bo = (size_t)r * K + k0 + seg * 8;                          \
            cp16(sb + 32768 + sw, Bh0 + bo, 16);                               \
            cp16(sb + 40960 + sw, Bl0 + bo, 16);                               \
        }                                                                      \
        asm volatile("cp.async.commit_group;" ::: "memory");                   \
    };                                                                         \
    const int a_off0 = (wm * 32 + (lane & 15)) * 128 + ((lane >> 4) << 4);     \
    const int b_off0 = (wn * 32 + ((lane >> 4) << 3) + (lane & 7)) * 128       \
                     + (((lane >> 3) & 1) << 4);                               \
    load_chunk(0);                                                             \
    for (int c = 0; c < nc; c++) {                                             \
        if (c + 1 < nc) {                                                      \
            load_chunk(c + 1);                                                 \
            asm volatile("cp.async.wait_group 1;" ::: "memory");               \
        } else {                                                               \
            asm volatile("cp.async.wait_group 0;" ::: "memory");               \
        }                                                                      \
        __syncthreads();                                                       \
        uint32_t sb = base0 + (uint32_t)(c & 1) * STAGE_BYTES;                 \
        _Pragma("unroll")                                                      \
        for (int kk = 0; kk < 4; kk++) {                                       \
            uint32_t ah[2][4], al[2][4], bh[2][4], bl[2][4];                   \
            _Pragma("unroll")                                                  \
            for (int mt = 0; mt < 2; mt++) {                                   \
                int off = a_off0 + mt * 2048 + kk * 32;                        \
                uint32_t sw = (uint32_t)(off ^ ((off >> 3) & 0x70));           \
                ldm_x4(ah[mt], sb + sw);                                       \
                ldm_x4(al[mt], sb + 16384 + sw);                               \
            }                                                                  \
            _Pragma("unroll")                                                  \
            for (int np = 0; np < 2; np++) {                                   \
                int off = b_off0 + np * 2048 + kk * 32;                        \
                uint32_t sw = (uint32_t)(off ^ ((off >> 3) & 0x70));           \
                ldm_x4(bh[np], sb + 32768 + sw);                               \
                ldm_x4(bl[np], sb + 40960 + sw);                               \
            }                                                                  \
            _Pragma("unroll")                                                  \
            for (int mt = 0; mt < 2; mt++)                                     \
                _Pragma("unroll")                                              \
                for (int nt = 0; nt < 4; nt++) {                               \
                    const uint32_t* bhp = &bh[nt >> 1][(nt & 1) * 2];          \
                    const uint32_t* blp = &bl[nt >> 1][(nt & 1) * 2];          \
                    mma_bf16(ACC[mt][nt], ah[mt], bhp);                        \
                    mma_bf16(ACC[mt][nt], ah[mt], blp);                        \
                    mma_bf16(ACC[mt][nt], al[mt], bhp);                        \
                }                                                              \
        }                                                                      \
        __syncthreads();                                                       \
    }

// ---------------- plain GEMM: C = act(A@B^T + bias) ----------------
__global__ void __launch_bounds__(256, 2)
mma_gemm(const __nv_bfloat16* __restrict__ Ah, const __nv_bfloat16* __restrict__ Al,
         const __nv_bfloat16* __restrict__ Bh, const __nv_bfloat16* __restrict__ Bl,
         const float* __restrict__ bias, float* __restrict__ C,
         int M, int K, int ldc, int nvalid, int relu) {
    GEMM_MAINLOOP(acc)
#pragma unroll
    for (int mt = 0; mt < 2; mt++) {
        int ra = row0 + wm * 32 + mt * 16 + (lane >> 2);
        int rb = ra + 8;
#pragma unroll
        for (int nt = 0; nt < 4; nt++) {
            int c0 = col0 + wn * 32 + nt * 8 + (lane & 3) * 2;
            float bv0 = 0.f, bv1 = 0.f;
            if (bias && c0 < nvalid) {
                bv0 = __ldg(&bias[c0]);
                bv1 = __ldg(&bias[c0 + 1]);
            }
            float v0 = acc[mt][nt][0] + bv0;
            float v1 = acc[mt][nt][1] + bv1;
            float v2 = acc[mt][nt][2] + bv0;
            float v3 = acc[mt][nt][3] + bv1;
            if (relu) {
                v0 = fmaxf(v0, 0.f); v1 = fmaxf(v1, 0.f);
                v2 = fmaxf(v2, 0.f); v3 = fmaxf(v3, 0.f);
            }
            if (ra < M) *(float2*)&C[(size_t)ra * ldc + c0] = make_float2(v0, v1);
            if (rb < M) *(float2*)&C[(size_t)rb * ldc + c0] = make_float2(v2, v3);
        }
    }
}

// ---------------- fused h+t GEMM ----------------
__global__ void __launch_bounds__(256, 2)
mma_gemm_fused(const __nv_bfloat16* __restrict__ Ah, const __nv_bfloat16* __restrict__ Al,
               const __nv_bfloat16* __restrict__ Bh, const __nv_bfloat16* __restrict__ Bl,
               const float* __restrict__ bias2,
               float* __restrict__ C1, float* __restrict__ C2,
               int M, int K) {
    GEMM_MAINLOOP(acc)
    float* C;
    int ldc, rel, cbase, nval;
    const float* bias;
    if (col0 < 256) {
        C = C1; ldc = HD; rel = 0; bias = nullptr; cbase = col0; nval = HD;
    } else {
        C = C2; ldc = TD2; rel = 1; bias = bias2; cbase = col0 - 256; nval = 400;
    }
#pragma unroll
    for (int mt = 0; mt < 2; mt++) {
        int ra = row0 + wm * 32 + mt * 16 + (lane >> 2);
        int rb = ra + 8;
#pragma unroll
        for (int nt = 0; nt < 4; nt++) {
            int c0 = cbase + wn * 32 + nt * 8 + (lane & 3) * 2;
            float bv0 = 0.f, bv1 = 0.f;
            if (bias && c0 < nval) {
                bv0 = __ldg(&bias[c0]);
                bv1 = __ldg(&bias[c0 + 1]);
            }
            float v0 = acc[mt][nt][0] + bv0;
            float v1 = acc[mt][nt][1] + bv1;
            float v2 = acc[mt][nt][2] + bv0;
            float v3 = acc[mt][nt][3] + bv1;
            if (rel) {
                v0 = fmaxf(v0, 0.f); v1 = fmaxf(v1, 0.f);
                v2 = fmaxf(v2, 0.f); v3 = fmaxf(v3, 0.f);
            }
            if (ra < M) *(float2*)&C[(size_t)ra * ldc + c0] = make_float2(v0, v1);
            if (rb < M) *(float2*)&C[(size_t)rb * ldc + c0] = make_float2(v2, v3);
        }
    }
}

// ---------------- conversion kernels ----------------
__global__ void xsplit_kernel(const float* __restrict__ x, long n) {
    long i = (long)blockIdx.x * blockDim.x + threadIdx.x;
    if (i < n) {
        float v = x[i];
        __nv_bfloat16 hi = __float2bfloat16(v);
        g_xhi[i] = hi;
        g_xlo[i] = __float2bfloat16(v - __bfloat162float(hi));
    }
}

__global__ void wsplit_kernel(const float* __restrict__ W, int K, int N,
                              int Nout, int Kpad, int slot, int row0) {
    int i = blockIdx.x * blockDim.x + threadIdx.x;
    if (i < Nout * Kpad) {
        int n = i / Kpad, k = i - n * Kpad;
        float v = (n < N && k < K) ? W[(size_t)k * N + n] : 0.f;
        __nv_bfloat16 hi = __float2bfloat16(v);
        size_t o = (size_t)slot * WSLOT + (size_t)(row0 + n) * Kpad + k;
        g_wh[o] = hi;
        g_wl[o] = __float2bfloat16(v - __bfloat162float(hi));
    }
}

__global__ void padzero_kernel() {
    int v = blockIdx.x, c = threadIdx.x;
    if (c < GDC - 456) {
        size_t o = (size_t)v * GDC + 456 + c;
        g_chi[o] = __float2bfloat16(0.f);
        g_clo[o] = __float2bfloat16(0.f);
    }
}

// ---------------- graph setup ----------------
__global__ void zero_deg_kernel() {
    int i = blockIdx.x * blockDim.x + threadIdx.x;
    if (i < NNODES) g_deg[i] = 0;
}

__global__ void count_deg_kernel(const int* __restrict__ dst) {
    for (int e = blockIdx.x * blockDim.x + threadIdx.x; e < NEDGES;
         e += gridDim.x * blockDim.x)
        atomicAdd(&g_deg[dst[e]], 1);
}

__global__ void scan1_kernel() {
    __shared__ int s[1024];
    int tid = threadIdx.x;
    int i = blockIdx.x * 1024 + tid;
    int v = (i < NNODES) ? g_deg[i] : 0;
    s[tid] = v;
    __syncthreads();
    for (int off = 1; off < 1024; off <<= 1) {
        int t = (tid >= off) ? s[tid - off] : 0;
        __syncthreads();
        s[tid] += t;
        __syncthreads();
    }
    if (i < NNODES) g_rowptr[i + 1] = s[tid];
    if (tid == 1023) g_bsum[blockIdx.x] = s[1023];
}

__global__ void scan2_kernel() {
    int acc = 0;
    for (int b = 0; b < 49; b++) { int t = g_bsum[b]; g_bsum[b] = acc; acc += t; }
}

__global__ void scan3_kernel() {
    int i = blockIdx.x * 1024 + threadIdx.x;
    if (i == 0) g_rowptr[0] = 0;
    if (i < NNODES) {
        int incl = g_rowptr[i + 1] + g_bsum[blockIdx.x];
        g_rowptr[i + 1] = incl;
        g_cur[i] = incl - g_deg[i];
        g_dis[i] = rsqrtf((float)(g_deg[i] + 1));
    }
}

__global__ void fill_csr_kernel(const int* __restrict__ src,
                                const int* __restrict__ dst) {
    for (int e = blockIdx.x * blockDim.x + threadIdx.x; e < NEDGES;
         e += gridDim.x * blockDim.x) {
        int d = dst[e];
        int p = atomicAdd(&g_cur[d], 1);
        g_colidx[p] = src[e];
    }
}

// ---------------- low-rank path ----------------
__global__ void zero_misc_kernel() {
    int i = blockIdx.x * blockDim.x + threadIdx.x;
    if (i < KLR * KLR) g_M[i] = 0.f;
    if (i < 2 * KLR)   g_cs[i] = 0.f;
    if (i < HD)        { g_mean[i] = 0.f; g_msq[i] = 0.f; }
}

__global__ void nf_kernel() {
    int lane = threadIdx.x;
    float s = 0.f;
    for (int k = lane; k < KLR; k += 32) s += g_cs[k] * g_cs[KLR + k];
#pragma unroll
    for (int o = 16; o > 0; o >>= 1) s += __shfl_down_sync(0xffffffffu, s, o);
    if (lane == 0) g_inv_nf = 1.0f / (s / (float)NNODES + 1e-6f);
}

// M = V^T @ Z (100x100) + column sums of U,V fused.
// 200 k-split blocks, 7x7 register tile per thread.
__global__ void __launch_bounds__(256) vtz_kernel() {
    __shared__ float Us[32][112];
    __shared__ float Vs[32][112];
    __shared__ float Zs[32][112];
    const int tid = threadIdx.x;
    const int i = tid >> 4;
    const int j = tid & 15;
    const int kbeg = blockIdx.x * 250;
    const int kend = min(kbeg + 250, NNODES);

    float acc[7][7];
#pragma unroll
    for (int p = 0; p < 7; p++)
#pragma unroll
        for (int q = 0; q < 7; q++) acc[p][q] = 0.f;
    float csum = 0.f;

    for (int k0 = kbeg; k0 < kend; k0 += 32) {
        int km = kend - k0;
        for (int idx = tid; idx < 32 * 112; idx += 256) {
            int kk = idx / 112, cc = idx - kk * 112;
            float u = 0.f, v = 0.f, z = 0.f;
            if (kk < km && cc < KLR) {
                size_t b = (size_t)(k0 + kk) * TD2;
                u = g_t[b + cc];
                v = g_t[b + KLR + cc];
                z = g_t[b + 2 * KLR + cc];
            }
            Us[kk][cc] = u;
            Vs[kk][cc] = v;
            Zs[kk][cc] = z;
        }
        __syncthreads();
        // column sums of U (cols 0..99) and V (cols 100..199)
        if (tid < 2 * KLR) {
            float s = 0.f;
#pragma unroll 8
            for (int kk = 0; kk < 32; kk++)
                s += (tid < KLR) ? Us[kk][tid] : Vs[kk][tid - KLR];
            csum += s;
        }
#pragma unroll 4
        for (int kk = 0; kk < 32; kk++) {
            float av[7], bz[7];
#pragma unroll
            for (int p = 0; p < 7; p++) av[p] = Vs[kk][i + 16 * p];
#pragma unroll
            for (int q = 0; q < 7; q++) bz[q] = Zs[kk][j + 16 * q];
#pragma unroll
            for (int p = 0; p < 7; p++)
#pragma unroll
                for (int q = 0; q < 7; q++)
                    acc[p][q] = fmaf(av[p], bz[q], acc[p][q]);
        }
        __syncthreads();
    }
    if (tid < 2 * KLR) atomicAdd(&g_cs[tid], csum);
#pragma unroll
    for (int p = 0; p < 7; p++) {
        int r = i + 16 * p;
        if (r >= KLR) break;
#pragma unroll
        for (int q = 0; q < 7; q++) {
            int c = j + 16 * q;
            if (c < KLR) atomicAdd(&g_M[r * KLR + c], acc[p][q]);
        }
    }
}

// packed combine cols 0..199 = [res/nf | T] as bf16 hi/lo
// 64 rows per block: 4 rows x 7 cols register tile per thread.
__global__ void __launch_bounds__(256) respack_kernel() {
    __shared__ float Msh[KLR * KLR];      // 40 KB
    __shared__ float Ush[64][KLR];        // 25.6 KB
    int tid = threadIdx.x;
    int r0 = blockIdx.x * 64;
    for (int idx = tid; idx < KLR * KLR; idx += 256) Msh[idx] = g_M[idx];
    for (int idx = tid; idx < 64 * KLR; idx += 256) {
        int r = idx / KLR, c = idx - r * KLR;
        Ush[r][c] = (r0 + r < NNODES) ? g_t[(size_t)(r0 + r) * TD2 + c] : 0.f;
    }
    __syncthreads();
    float inv = g_inv_nf;
    int rg = tid >> 4;   // 0..15
    int cg = tid & 15;   // 0..15

    float acc[4][7];
#pragma unroll
    for (int jj = 0; jj < 4; jj++)
#pragma unroll
        for (int q = 0; q < 7; q++) acc[jj][q] = 0.f;

    for (int k = 0; k < KLR; k++) {
        float m[7];
#pragma unroll
        for (int q = 0; q < 7; q++) {
            int c = cg + 16 * q;
            m[q] = (c < KLR) ? Msh[k * KLR + c] : 0.f;
        }
#pragma unroll
        for (int jj = 0; jj < 4; jj++) {
            float a = Ush[rg + 16 * jj][k];
#pragma unroll
            for (int q = 0; q < 7; q++)
                acc[jj][q] = fmaf(a, m[q], acc[jj][q]);
        }
    }
#pragma unroll
    for (int jj = 0; jj < 4; jj++) {
        int r = r0 + rg + 16 * jj;
        if (r >= NNODES) continue;
        size_t base = (size_t)r * GDC;
#pragma unroll
        for (int q = 0; q < 7; q++) {
            int c = cg + 16 * q;
            if (c < KLR) {
                float v = acc[jj][q] * inv;
                __nv_bfloat16 hi = __float2bfloat16(v);
                g_chi[base + c] = hi;
                g_clo[base + c] = __float2bfloat16(v - __bfloat162float(hi));
            }
        }
#pragma unroll
        for (int q = 0; q < 7; q++) {
            int c = cg + 16 * q;
            if (c < KLR) {
                float v = g_t[(size_t)r * TD2 + 3 * KLR + c];
                __nv_bfloat16 hi = __float2bfloat16(v);
                g_chi[base + KLR + c] = hi;
                g_clo[base + KLR + c] = __float2bfloat16(v - __bfloat162float(hi));
            }
        }
    }
}

// cols 200..455 of combine input = relu(aggregate + cb) as bf16 hi/lo
__global__ void agg_kernel(const float* __restrict__ cb) {
    __shared__ int   sh_u[64];
    __shared__ float sh_w[64];
    const int v = blockIdx.x;
    const int c = threadIdx.x;
    const float dv = g_dis[v];
    float acc = g_h[(size_t)v * HD + c] * dv * dv;
    const int s0 = g_rowptr[v], e0 = g_rowptr[v + 1];
    for (int s = s0; s < e0; s += 64) {
        int m = min(64, e0 - s);
        __syncthreads();
        if (c < m) {
            int u = g_colidx[s + c];
            sh_u[c] = u;
            sh_w[c] = g_dis[u] * dv;
        }
        __syncthreads();
        int j = 0;
        for (; j + 4 <= m; j += 4) {
            float h0 = g_h[(size_t)sh_u[j + 0] * HD + c];
            float h1 = g_h[(size_t)sh_u[j + 1] * HD + c];
            float h2 = g_h[(size_t)sh_u[j + 2] * HD + c];
            float h3 = g_h[(size_t)sh_u[j + 3] * HD + c];
            acc = fmaf(h0, sh_w[j + 0], acc);
            acc = fmaf(h1, sh_w[j + 1], acc);
            acc = fmaf(h2, sh_w[j + 2], acc);
            acc = fmaf(h3, sh_w[j + 3], acc);
        }
        for (; j < m; j++)
            acc = fmaf(g_h[(size_t)sh_u[j] * HD + c], sh_w[j], acc);
    }
    acc = fmaxf(acc + cb[c], 0.f);
    __nv_bfloat16 hi = __float2bfloat16(acc);
    size_t o = (size_t)v * GDC + 200 + c;
    g_chi[o] = hi;
    g_clo[o] = __float2bfloat16(acc - __bfloat162float(hi));
}

// ---------------- batch norm ----------------
__global__ void bn_stats_kernel() {
    int col = threadIdx.x;
    int r0 = blockIdx.x * 128;
    int rend = min(r0 + 128, NNODES);
    float s = 0.f, s2 = 0.f;
    for (int r = r0; r < rend; r++) {
        float v = g_x[(size_t)r * HD + col];
        s += v;
        s2 = fmaf(v, v, s2);
    }
    atomicAdd(&g_mean[col], s);
    atomicAdd(&g_msq[col], s2);
}

// scale/shift computed inline from raw sums (bn_final eliminated)
__global__ void bn_apply_kernel(const float* __restrict__ gam,
                                const float* __restrict__ bet) {
    size_t i = (size_t)blockIdx.x * blockDim.x + threadIdx.x;
    if (i < (size_t)NNODES * HD) {
        int c = (int)(i & (HD - 1));
        float m = g_mean[c] * (1.f / NNODES);
        float var = g_msq[c] * (1.f / NNODES) - m * m;
        float sc = __ldg(&gam[c]) * rsqrtf(var + 1e-5f);
        float sh = __ldg(&bet[c]) - m * sc;
        float v = fmaf(g_x[i], sc, sh);
        __nv_bfloat16 hi = __float2bfloat16(v);
        g_xhi[i] = hi;
        g_xlo[i] = __float2bfloat16(v - __bfloat162float(hi));
    }
}

// ---------------- host orchestration ----------------
extern "C" void kernel_launch(void* const* d_in, const int* in_sizes, int n_in,
                              void* d_out, int out_size) {
    (void)in_sizes; (void)n_in; (void)out_size;
    const float* x_in = (const float*)d_in[0];
    const int*   ei   = (const int*)d_in[1];
    const int*   src  = ei;
    const int*   dst  = ei + NEDGES;

    const float* cw[3] = {(const float*)d_in[2],  (const float*)d_in[8],  (const float*)d_in[14]};
    const float* cb[3] = {(const float*)d_in[3],  (const float*)d_in[9],  (const float*)d_in[15]};
    const float* aw[3] = {(const float*)d_in[4],  (const float*)d_in[10], (const float*)d_in[16]};
    const float* ab[3] = {(const float*)d_in[5],  (const float*)d_in[11], (const float*)d_in[17]};
    const float* rw[3] = {(const float*)d_in[6],  (const float*)d_in[12], (const float*)d_in[18]};
    const float* rb[3] = {(const float*)d_in[7],  (const float*)d_in[13], (const float*)d_in[19]};
    const float* gam[2] = {(const float*)d_in[20], (const float*)d_in[22]};
    const float* bet[2] = {(const float*)d_in[21], (const float*)d_in[23]};
    float* out = (float*)d_out;

    float *p_x, *p_h, *p_t;
    __nv_bfloat16 *p_xhi, *p_xlo, *p_chi, *p_clo, *p_wh, *p_wl;
    cudaGetSymbolAddress((void**)&p_x, g_x);
    cudaGetSymbolAddress((void**)&p_h, g_h);
    cudaGetSymbolAddress((void**)&p_t, g_t);
    cudaGetSymbolAddress((void**)&p_xhi, g_xhi);
    cudaGetSymbolAddress((void**)&p_xlo, g_xlo);
    cudaGetSymbolAddress((void**)&p_chi, g_chi);
    cudaGetSymbolAddress((void**)&p_clo, g_clo);
    cudaGetSymbolAddress((void**)&p_wh, g_wh);
    cudaGetSymbolAddress((void**)&p_wl, g_wl);

    const int SMB = 2 * STAGE_BYTES + 1024;

    static cudaStream_t s2 = nullptr, s3 = nullptr;
    static cudaEvent_t evFork = nullptr, evH = nullptr, evAgg = nullptr;
    static cudaEvent_t evW03 = nullptr, evW = nullptr;
    if (s2 == nullptr) {
        cudaFuncSetAttribute(mma_gemm, cudaFuncAttributeMaxDynamicSharedMemorySize, SMB);
        cudaFuncSetAttribute(mma_gemm_fused, cudaFuncAttributeMaxDynamicSharedMemorySize, SMB);
        cudaStreamCreateWithFlags(&s2, cudaStreamNonBlocking);
        cudaStreamCreateWithFlags(&s3, cudaStreamNonBlocking);
        cudaEventCreateWithFlags(&evFork, cudaEventDisableTiming);
        cudaEventCreateWithFlags(&evH, cudaEventDisableTiming);
        cudaEventCreateWithFlags(&evAgg, cudaEventDisableTiming);
        cudaEventCreateWithFlags(&evW03, cudaEventDisableTiming);
        cudaEventCreateWithFlags(&evW, cudaEventDisableTiming);
    }

    // ---- fork: CSR setup on s2, weight pre-split on s3 ----
    cudaEventRecord(evFork, 0);
    cudaStreamWaitEvent(s2, evFork, 0);
    cudaStreamWaitEvent(s3, evFork, 0);

    padzero_kernel<<<NNODES, 64, 0, s2>>>();
    zero_deg_kernel<<<(NNODES + 255) / 256, 256, 0, s2>>>();
    count_deg_kernel<<<800, 256, 0, s2>>>(dst);
    scan1_kernel<<<49, 1024, 0, s2>>>();
    scan2_kernel<<<1, 1, 0, s2>>>();
    scan3_kernel<<<49, 1024, 0, s2>>>();
    fill_csr_kernel<<<800, 256, 0, s2>>>(src, dst);

    const int dinv[3] = {128, 256, 256};
    for (int l = 0; l < 3; l++) {
        int K = dinv[l];
        int n1 = 256 * K;
        wsplit_kernel<<<(n1 + 255) / 256, 256, 0, s3>>>(cw[l], K, 256, 256, K, 3 * l, 0);
        int n2 = 448 * K;
        wsplit_kernel<<<(n2 + 255) / 256, 256, 0, s3>>>(aw[l], K, 400, 448, K, 3 * l, 256);
        int dout = (l < 2) ? 256 : 128;
        int n3 = dout * 512;
        wsplit_kernel<<<(n3 + 255) / 256, 256, 0, s3>>>(rw[l], 456, dout, dout, 512, 3 * l + 2, 0);
        if (l == 0) cudaEventRecord(evW03, s3);
    }
    cudaEventRecord(evW, s3);

    // ---- main stream: input conversion; wait only for layer-0 weights ----
    xsplit_kernel<<<(NNODES * 128 + 255) / 256, 256>>>(x_in, (long)NNODES * 128);
    cudaStreamWaitEvent(0, evW03, 0);

    for (int l = 0; l < 3; l++) {
        if (l == 1) cudaStreamWaitEvent(0, evW, 0);
        int din = dinv[l];
        const __nv_bfloat16* sh = p_wh + (size_t)(3 * l) * WSLOT;
        const __nv_bfloat16* sl = p_wl + (size_t)(3 * l) * WSLOT;
        const __nv_bfloat16* rwh = p_wh + (size_t)(3 * l + 2) * WSLOT;
        const __nv_bfloat16* rwl = p_wl + (size_t)(3 * l + 2) * WSLOT;

        // fused: h = x@cw ; t = relu(x@aw + ab)  (11 column tiles)
        mma_gemm_fused<<<dim3(11, MB), 256, SMB>>>(
            p_xhi, p_xlo, sh, sl, ab[l], p_h, p_t, NNODES, din);
        cudaEventRecord(evH, 0);

        // side stream: aggregation
        cudaStreamWaitEvent(s2, evH, 0);
        agg_kernel<<<NNODES, HD, 0, s2>>>(cb[l]);
        cudaEventRecord(evAgg, s2);

        // main: low-rank path (vtz also produces colsum -> g_cs)
        zero_misc_kernel<<<(KLR * KLR + 255) / 256, 256>>>();
        vtz_kernel<<<200, 256>>>();
        nf_kernel<<<1, 32>>>();
        respack_kernel<<<(NNODES + 63) / 64, 256>>>();

        // join: combine needs agg output
        cudaStreamWaitEvent(0, evAgg, 0);
        if (l < 2) {
            mma_gemm<<<dim3(HD / 64, MB), 256, SMB>>>(
                p_chi, p_clo, rwh, rwl, rb[l], p_x, NNODES, GDC, HD, HD, 1);
            bn_stats_kernel<<<(NNODES + 127) / 128, 256>>>();
            bn_apply_kernel<<<(NNODES * HD + 255) / 256, 256>>>(gam[l], bet[l]);
        } else {
            mma_gemm<<<dim3(2, MB), 256, SMB>>>(
                p_chi, p_clo, rwh, rwl, rb[l], out, NNODES, GDC, 128, 128, 0);
        }
    }
}

// round 14
// speedup vs baseline: 1.3952x; 1.1282x over previous
#include <cuda_runtime.h>
#include <cuda_fp16.h>
#include <cstdint>

// ---------------- problem constants ----------------
#define NNODES 50000
#define NEDGES 800000
#define HD     256
#define TD2    512
#define GDC    512
#define KLR    100
#define MB     391
#define WSLOT  (512 * 512)

// ---------------- static scratch ----------------
__device__ float g_x[NNODES * HD];
__device__ float g_h[NNODES * HD];
__device__ float g_t[NNODES * TD2];
__device__ __half g_xa[NNODES * HD];        // activations, single fp16
__device__ __half g_ca[NNODES * GDC];       // combine input, single fp16
__device__ __half g_wh[9 * WSLOT];          // weights hi (fp16)
__device__ __half g_wl[9 * WSLOT];          // weights lo (fp16)
__device__ float g_M[KLR * KLR];
__device__ float g_cs[2 * KLR];
__device__ float g_inv_nf;
__device__ float g_mean[HD];
__device__ float g_msq[HD];
__device__ float g_dis[NNODES];
__device__ int   g_deg[NNODES];
__device__ int   g_rowptr[NNODES + 1];
__device__ int   g_cur[NNODES];
__device__ int   g_colidx[NEDGES];
__device__ int   g_bsum[64];

// ---------------- PTX helpers ----------------
__device__ __forceinline__ uint32_t smem_u32(const void* p) {
    uint32_t a;
    asm("{ .reg .u64 t; cvta.to.shared.u64 t, %1; cvt.u32.u64 %0, t; }"
        : "=r"(a) : "l"(p));
    return a;
}

__device__ __forceinline__ void cp16(uint32_t dst, const void* src, int sz) {
    asm volatile("cp.async.cg.shared.global [%0], [%1], 16, %2;"
                 :: "r"(dst), "l"(src), "r"(sz) : "memory");
}

__device__ __forceinline__ void ldm_x4(uint32_t* r, uint32_t addr) {
    asm volatile("ldmatrix.sync.aligned.m8n8.x4.shared.b16 {%0,%1,%2,%3}, [%4];"
                 : "=r"(r[0]), "=r"(r[1]), "=r"(r[2]), "=r"(r[3]) : "r"(addr));
}

__device__ __forceinline__ void mma_f16(float* d, const uint32_t* a,
                                        const uint32_t* b) {
    asm volatile(
        "mma.sync.aligned.m16n8k16.row.col.f32.f16.f16.f32 "
        "{%0,%1,%2,%3}, {%4,%5,%6,%7}, {%8,%9}, {%0,%1,%2,%3};"
        : "+f"(d[0]), "+f"(d[1]), "+f"(d[2]), "+f"(d[3])
        : "r"(a[0]), "r"(a[1]), "r"(a[2]), "r"(a[3]), "r"(b[0]), "r"(b[1]));
}

// ---------------- shared GEMM mainloop (fp16 2-product) ----------------
// A single fp16 [M x K]; B = Bh + Bl fp16 split, transposed [Nout x K].
// CTA tile 128 x 64, BK=64, 8 warps 4(M)x2(N), warp tile 32x32.
// smem/stage: A 16KB @0, Bh 8KB @16384, Bl 8KB @24576. 2 stages, 2 CTAs/SM.
#define STAGE_BYTES 32768

#define GEMM_MAINLOOP(ACC)                                                     \
    extern __shared__ char dsm_raw[];                                          \
    uint32_t base0 = (smem_u32(dsm_raw) + 1023u) & ~1023u;                     \
    const int tid = threadIdx.x;                                               \
    const int wid = tid >> 5;                                                  \
    const int lane = tid & 31;                                                 \
    const int wm = wid & 3;                                                    \
    const int wn = wid >> 2;                                                   \
    const int row0 = blockIdx.y * 128;                                         \
    const int col0 = blockIdx.x * 64;                                          \
    const __half* Bh0 = Bh + (size_t)col0 * K;                                 \
    const __half* Bl0 = Bl + (size_t)col0 * K;                                 \
    const int nc = K >> 6;                                                     \
    float ACC[2][4][4];                                                        \
    _Pragma("unroll")                                                          \
    for (int mt = 0; mt < 2; mt++)                                             \
        _Pragma("unroll")                                                      \
        for (int nt = 0; nt < 4; nt++)                                         \
            _Pragma("unroll")                                                  \
            for (int q = 0; q < 4; q++) ACC[mt][nt][q] = 0.f;                  \
    auto load_chunk = [&](int c) {                                             \
        uint32_t sb = base0 + (uint32_t)(c & 1) * STAGE_BYTES;                 \
        int k0 = c << 6;                                                       \
        _Pragma("unroll 4")                                                    \
        for (int j = 0; j < 4; j++) {                                          \
            int i = tid + j * 256;                                             \
            int r = i >> 3, seg = i & 7;                                       \
            int off = r * 128 + seg * 16;                                      \
            uint32_t sw = (uint32_t)(off ^ ((off >> 3) & 0x70));               \
            int ga = row0 + r;                                                 \
            int ok = (ga < M) ? 16 : 0;                                        \
            if (ga >= M) ga = 0;                                               \
            size_t ao = (size_t)ga * K + k0 + seg * 8;                         \
            cp16(sb + sw, A + ao, ok);                                         \
        }                                                                      \
        {                                                                      \
            int i = tid;                                                       \
            int r = i >> 3, seg = i & 7;                                       \
            int off = r * 128 + seg * 16;                                      \
            uint32_t sw = (uint32_t)(off ^ ((off >> 3) & 0x70));               \
            size_t bo = (size_t)r * K + k0 + seg * 8;                          \
            cp16(sb + 16384 + sw, Bh0 + bo, 16);                               \
            cp16(sb + 24576 + sw, Bl0 + bo, 16);                               \
        }                                                                      \
        {                                                                      \
            int i = tid + 256;                                                 \
            int r = i >> 3, seg = i & 7;                                       \
            int off = r * 128 + seg * 16;                                      \
            uint32_t sw = (uint32_t)(off ^ ((off >> 3) & 0x70));               \
            size_t bo = (size_t)r * K + k0 + seg * 8;                          \
            cp16(sb + 16384 + sw, Bh0 + bo, 16);                               \
            cp16(sb + 24576 + sw, Bl0 + bo, 16);                               \
        }                                                                      \
        asm volatile("cp.async.commit_group;" ::: "memory");                   \
    };                                                                         \
    const int a_off0 = (wm * 32 + (lane & 15)) * 128 + ((lane >> 4) << 4);     \
    const int b_off0 = (wn * 32 + ((lane >> 4) << 3) + (lane & 7)) * 128       \
                     + (((lane >> 3) & 1) << 4);                               \
    load_chunk(0);                                                             \
    for (int c = 0; c < nc; c++) {                                             \
        if (c + 1 < nc) {                                                      \
            load_chunk(c + 1);                                                 \
            asm volatile("cp.async.wait_group 1;" ::: "memory");               \
        } else {                                                               \
            asm volatile("cp.async.wait_group 0;" ::: "memory");               \
        }                                                                      \
        __syncthreads();                                                       \
        uint32_t sb = base0 + (uint32_t)(c & 1) * STAGE_BYTES;                 \
        _Pragma("unroll")                                                      \
        for (int kk = 0; kk < 4; kk++) {                                       \
            uint32_t ah[2][4], bh[2][4], bl[2][4];                             \
            _Pragma("unroll")                                                  \
            for (int mt = 0; mt < 2; mt++) {                                   \
                int off = a_off0 + mt * 2048 + kk * 32;                        \
                uint32_t sw = (uint32_t)(off ^ ((off >> 3) & 0x70));           \
                ldm_x4(ah[mt], sb + sw);                                       \
            }                                                                  \
            _Pragma("unroll")                                                  \
            for (int np = 0; np < 2; np++) {                                   \
                int off = b_off0 + np * 2048 + kk * 32;                        \
                uint32_t sw = (uint32_t)(off ^ ((off >> 3) & 0x70));           \
                ldm_x4(bh[np], sb + 16384 + sw);                               \
                ldm_x4(bl[np], sb + 24576 + sw);                               \
            }                                                                  \
            _Pragma("unroll")                                                  \
            for (int mt = 0; mt < 2; mt++)                                     \
                _Pragma("unroll")                                              \
                for (int nt = 0; nt < 4; nt++) {                               \
                    const uint32_t* bhp = &bh[nt >> 1][(nt & 1) * 2];          \
                    const uint32_t* blp = &bl[nt >> 1][(nt & 1) * 2];          \
                    mma_f16(ACC[mt][nt], ah[mt], bhp);                         \
                    mma_f16(ACC[mt][nt], ah[mt], blp);                         \
                }                                                              \
        }                                                                      \
        __syncthreads();                                                       \
    }

// ---------------- plain GEMM: C = act(A@B^T + bias) ----------------
__global__ void __launch_bounds__(256, 2)
mma_gemm(const __half* __restrict__ A,
         const __half* __restrict__ Bh, const __half* __restrict__ Bl,
         const float* __restrict__ bias, float* __restrict__ C,
         int M, int K, int ldc, int nvalid, int relu) {
    GEMM_MAINLOOP(acc)
#pragma unroll
    for (int mt = 0; mt < 2; mt++) {
        int ra = row0 + wm * 32 + mt * 16 + (lane >> 2);
        int rb = ra + 8;
#pragma unroll
        for (int nt = 0; nt < 4; nt++) {
            int c0 = col0 + wn * 32 + nt * 8 + (lane & 3) * 2;
            float bv0 = 0.f, bv1 = 0.f;
            if (bias && c0 < nvalid) {
                bv0 = __ldg(&bias[c0]);
                bv1 = __ldg(&bias[c0 + 1]);
            }
            float v0 = acc[mt][nt][0] + bv0;
            float v1 = acc[mt][nt][1] + bv1;
            float v2 = acc[mt][nt][2] + bv0;
            float v3 = acc[mt][nt][3] + bv1;
            if (relu) {
                v0 = fmaxf(v0, 0.f); v1 = fmaxf(v1, 0.f);
                v2 = fmaxf(v2, 0.f); v3 = fmaxf(v3, 0.f);
            }
            if (ra < M) *(float2*)&C[(size_t)ra * ldc + c0] = make_float2(v0, v1);
            if (rb < M) *(float2*)&C[(size_t)rb * ldc + c0] = make_float2(v2, v3);
        }
    }
}

// ---------------- fused h+t GEMM ----------------
__global__ void __launch_bounds__(256, 2)
mma_gemm_fused(const __half* __restrict__ A,
               const __half* __restrict__ Bh, const __half* __restrict__ Bl,
               const float* __restrict__ bias2,
               float* __restrict__ C1, float* __restrict__ C2,
               int M, int K) {
    GEMM_MAINLOOP(acc)
    float* C;
    int ldc, rel, cbase, nval;
    const float* bias;
    if (col0 < 256) {
        C = C1; ldc = HD; rel = 0; bias = nullptr; cbase = col0; nval = HD;
    } else {
        C = C2; ldc = TD2; rel = 1; bias = bias2; cbase = col0 - 256; nval = 400;
    }
#pragma unroll
    for (int mt = 0; mt < 2; mt++) {
        int ra = row0 + wm * 32 + mt * 16 + (lane >> 2);
        int rb = ra + 8;
#pragma unroll
        for (int nt = 0; nt < 4; nt++) {
            int c0 = cbase + wn * 32 + nt * 8 + (lane & 3) * 2;
            float bv0 = 0.f, bv1 = 0.f;
            if (bias && c0 < nval) {
                bv0 = __ldg(&bias[c0]);
                bv1 = __ldg(&bias[c0 + 1]);
            }
            float v0 = acc[mt][nt][0] + bv0;
            float v1 = acc[mt][nt][1] + bv1;
            float v2 = acc[mt][nt][2] + bv0;
            float v3 = acc[mt][nt][3] + bv1;
            if (rel) {
                v0 = fmaxf(v0, 0.f); v1 = fmaxf(v1, 0.f);
                v2 = fmaxf(v2, 0.f); v3 = fmaxf(v3, 0.f);
            }
            if (ra < M) *(float2*)&C[(size_t)ra * ldc + c0] = make_float2(v0, v1);
            if (rb < M) *(float2*)&C[(size_t)rb * ldc + c0] = make_float2(v2, v3);
        }
    }
}

// ---------------- conversion kernels ----------------
__global__ void xsplit_kernel(const float* __restrict__ x, long n) {
    long i = (long)blockIdx.x * blockDim.x + threadIdx.x;
    if (i < n) g_xa[i] = __float2half(x[i]);
}

// W[K x N] fp32 -> transposed padded fp16 hi/lo into slot rows [row0, row0+Nout)
__global__ void wsplit_kernel(const float* __restrict__ W, int K, int N,
                              int Nout, int Kpad, int slot, int row0) {
    int i = blockIdx.x * blockDim.x + threadIdx.x;
    if (i < Nout * Kpad) {
        int n = i / Kpad, k = i - n * Kpad;
        float v = (n < N && k < K) ? W[(size_t)k * N + n] : 0.f;
        __half hi = __float2half(v);
        size_t o = (size_t)slot * WSLOT + (size_t)(row0 + n) * Kpad + k;
        g_wh[o] = hi;
        g_wl[o] = __float2half(v - __half2float(hi));
    }
}

__global__ void padzero_kernel() {
    int v = blockIdx.x, c = threadIdx.x;
    if (c < GDC - 456) {
        size_t o = (size_t)v * GDC + 456 + c;
        g_ca[o] = __float2half(0.f);
    }
}

// ---------------- graph setup ----------------
__global__ void zero_deg_kernel() {
    int i = blockIdx.x * blockDim.x + threadIdx.x;
    if (i < NNODES) g_deg[i] = 0;
}

__global__ void count_deg_kernel(const int* __restrict__ dst) {
    for (int e = blockIdx.x * blockDim.x + threadIdx.x; e < NEDGES;
         e += gridDim.x * blockDim.x)
        atomicAdd(&g_deg[dst[e]], 1);
}

__global__ void scan1_kernel() {
    __shared__ int s[1024];
    int tid = threadIdx.x;
    int i = blockIdx.x * 1024 + tid;
    int v = (i < NNODES) ? g_deg[i] : 0;
    s[tid] = v;
    __syncthreads();
    for (int off = 1; off < 1024; off <<= 1) {
        int t = (tid >= off) ? s[tid - off] : 0;
        __syncthreads();
        s[tid] += t;
        __syncthreads();
    }
    if (i < NNODES) g_rowptr[i + 1] = s[tid];
    if (tid == 1023) g_bsum[blockIdx.x] = s[1023];
}

__global__ void scan2_kernel() {
    int acc = 0;
    for (int b = 0; b < 49; b++) { int t = g_bsum[b]; g_bsum[b] = acc; acc += t; }
}

__global__ void scan3_kernel() {
    int i = blockIdx.x * 1024 + threadIdx.x;
    if (i == 0) g_rowptr[0] = 0;
    if (i < NNODES) {
        int incl = g_rowptr[i + 1] + g_bsum[blockIdx.x];
        g_rowptr[i + 1] = incl;
        g_cur[i] = incl - g_deg[i];
        g_dis[i] = rsqrtf((float)(g_deg[i] + 1));
    }
}

__global__ void fill_csr_kernel(const int* __restrict__ src,
                                const int* __restrict__ dst) {
    for (int e = blockIdx.x * blockDim.x + threadIdx.x; e < NEDGES;
         e += gridDim.x * blockDim.x) {
        int d = dst[e];
        int p = atomicAdd(&g_cur[d], 1);
        g_colidx[p] = src[e];
    }
}

// ---------------- low-rank path ----------------
__global__ void zero_misc_kernel() {
    int i = blockIdx.x * blockDim.x + threadIdx.x;
    if (i < KLR * KLR) g_M[i] = 0.f;
    if (i < 2 * KLR)   g_cs[i] = 0.f;
    if (i < HD)        { g_mean[i] = 0.f; g_msq[i] = 0.f; }
}

__global__ void nf_kernel() {
    int lane = threadIdx.x;
    float s = 0.f;
    for (int k = lane; k < KLR; k += 32) s += g_cs[k] * g_cs[KLR + k];
#pragma unroll
    for (int o = 16; o > 0; o >>= 1) s += __shfl_down_sync(0xffffffffu, s, o);
    if (lane == 0) g_inv_nf = 1.0f / (s / (float)NNODES + 1e-6f);
}

// M = V^T @ Z (100x100) + column sums of U,V fused.
__global__ void __launch_bounds__(256) vtz_kernel() {
    __shared__ float Us[32][112];
    __shared__ float Vs[32][112];
    __shared__ float Zs[32][112];
    const int tid = threadIdx.x;
    const int i = tid >> 4;
    const int j = tid & 15;
    const int kbeg = blockIdx.x * 250;
    const int kend = min(kbeg + 250, NNODES);

    float acc[7][7];
#pragma unroll
    for (int p = 0; p < 7; p++)
#pragma unroll
        for (int q = 0; q < 7; q++) acc[p][q] = 0.f;
    float csum = 0.f;

    for (int k0 = kbeg; k0 < kend; k0 += 32) {
        int km = kend - k0;
        for (int idx = tid; idx < 32 * 112; idx += 256) {
            int kk = idx / 112, cc = idx - kk * 112;
            float u = 0.f, v = 0.f, z = 0.f;
            if (kk < km && cc < KLR) {
                size_t b = (size_t)(k0 + kk) * TD2;
                u = g_t[b + cc];
                v = g_t[b + KLR + cc];
                z = g_t[b + 2 * KLR + cc];
            }
            Us[kk][cc] = u;
            Vs[kk][cc] = v;
            Zs[kk][cc] = z;
        }
        __syncthreads();
        if (tid < 2 * KLR) {
            float s = 0.f;
#pragma unroll 8
            for (int kk = 0; kk < 32; kk++)
                s += (tid < KLR) ? Us[kk][tid] : Vs[kk][tid - KLR];
            csum += s;
        }
#pragma unroll 4
        for (int kk = 0; kk < 32; kk++) {
            float av[7], bz[7];
#pragma unroll
            for (int p = 0; p < 7; p++) av[p] = Vs[kk][i + 16 * p];
#pragma unroll
            for (int q = 0; q < 7; q++) bz[q] = Zs[kk][j + 16 * q];
#pragma unroll
            for (int p = 0; p < 7; p++)
#pragma unroll
                for (int q = 0; q < 7; q++)
                    acc[p][q] = fmaf(av[p], bz[q], acc[p][q]);
        }
        __syncthreads();
    }
    if (tid < 2 * KLR) atomicAdd(&g_cs[tid], csum);
#pragma unroll
    for (int p = 0; p < 7; p++) {
        int r = i + 16 * p;
        if (r >= KLR) break;
#pragma unroll
        for (int q = 0; q < 7; q++) {
            int c = j + 16 * q;
            if (c < KLR) atomicAdd(&g_M[r * KLR + c], acc[p][q]);
        }
    }
}

// combine cols 0..199 = [res/nf | T] as fp16; 64 rows/block, 4x7 tile/thread
__global__ void __launch_bounds__(256) respack_kernel() {
    __shared__ float Msh[KLR * KLR];
    __shared__ float Ush[64][KLR];
    int tid = threadIdx.x;
    int r0 = blockIdx.x * 64;
    for (int idx = tid; idx < KLR * KLR; idx += 256) Msh[idx] = g_M[idx];
    for (int idx = tid; idx < 64 * KLR; idx += 256) {
        int r = idx / KLR, c = idx - r * KLR;
        Ush[r][c] = (r0 + r < NNODES) ? g_t[(size_t)(r0 + r) * TD2 + c] : 0.f;
    }
    __syncthreads();
    float inv = g_inv_nf;
    int rg = tid >> 4;
    int cg = tid & 15;

    float acc[4][7];
#pragma unroll
    for (int jj = 0; jj < 4; jj++)
#pragma unroll
        for (int q = 0; q < 7; q++) acc[jj][q] = 0.f;

    for (int k = 0; k < KLR; k++) {
        float m[7];
#pragma unroll
        for (int q = 0; q < 7; q++) {
            int c = cg + 16 * q;
            m[q] = (c < KLR) ? Msh[k * KLR + c] : 0.f;
        }
#pragma unroll
        for (int jj = 0; jj < 4; jj++) {
            float a = Ush[rg + 16 * jj][k];
#pragma unroll
            for (int q = 0; q < 7; q++)
                acc[jj][q] = fmaf(a, m[q], acc[jj][q]);
        }
    }
#pragma unroll
    for (int jj = 0; jj < 4; jj++) {
        int r = r0 + rg + 16 * jj;
        if (r >= NNODES) continue;
        size_t base = (size_t)r * GDC;
#pragma unroll
        for (int q = 0; q < 7; q++) {
            int c = cg + 16 * q;
            if (c < KLR) g_ca[base + c] = __float2half(acc[jj][q] * inv);
        }
#pragma unroll
        for (int q = 0; q < 7; q++) {
            int c = cg + 16 * q;
            if (c < KLR)
                g_ca[base + KLR + c] =
                    __float2half(g_t[(size_t)r * TD2 + 3 * KLR + c]);
        }
    }
}

// combine cols 200..455 = relu(aggregate + cb) as fp16
__global__ void agg_kernel(const float* __restrict__ cb) {
    __shared__ int   sh_u[64];
    __shared__ float sh_w[64];
    const int v = blockIdx.x;
    const int c = threadIdx.x;
    const float dv = g_dis[v];
    float acc = g_h[(size_t)v * HD + c] * dv * dv;
    const int s0 = g_rowptr[v], e0 = g_rowptr[v + 1];
    for (int s = s0; s < e0; s += 64) {
        int m = min(64, e0 - s);
        __syncthreads();
        if (c < m) {
            int u = g_colidx[s + c];
            sh_u[c] = u;
            sh_w[c] = g_dis[u] * dv;
        }
        __syncthreads();
        int j = 0;
        for (; j + 4 <= m; j += 4) {
            float h0 = g_h[(size_t)sh_u[j + 0] * HD + c];
            float h1 = g_h[(size_t)sh_u[j + 1] * HD + c];
            float h2 = g_h[(size_t)sh_u[j + 2] * HD + c];
            float h3 = g_h[(size_t)sh_u[j + 3] * HD + c];
            acc = fmaf(h0, sh_w[j + 0], acc);
            acc = fmaf(h1, sh_w[j + 1], acc);
            acc = fmaf(h2, sh_w[j + 2], acc);
            acc = fmaf(h3, sh_w[j + 3], acc);
        }
        for (; j < m; j++)
            acc = fmaf(g_h[(size_t)sh_u[j] * HD + c], sh_w[j], acc);
    }
    acc = fmaxf(acc + cb[c], 0.f);
    g_ca[(size_t)v * GDC + 200 + c] = __float2half(acc);
}

// ---------------- batch norm ----------------
__global__ void bn_stats_kernel() {
    int col = threadIdx.x;
    int r0 = blockIdx.x * 128;
    int rend = min(r0 + 128, NNODES);
    float s = 0.f, s2 = 0.f;
    for (int r = r0; r < rend; r++) {
        float v = g_x[(size_t)r * HD + col];
        s += v;
        s2 = fmaf(v, v, s2);
    }
    atomicAdd(&g_mean[col], s);
    atomicAdd(&g_msq[col], s2);
}

__global__ void bn_apply_kernel(const float* __restrict__ gam,
                                const float* __restrict__ bet) {
    size_t i = (size_t)blockIdx.x * blockDim.x + threadIdx.x;
    if (i < (size_t)NNODES * HD) {
        int c = (int)(i & (HD - 1));
        float m = g_mean[c] * (1.f / NNODES);
        float var = g_msq[c] * (1.f / NNODES) - m * m;
        float sc = __ldg(&gam[c]) * rsqrtf(var + 1e-5f);
        float sh = __ldg(&bet[c]) - m * sc;
        g_xa[i] = __float2half(fmaf(g_x[i], sc, sh));
    }
}

// ---------------- host orchestration ----------------
extern "C" void kernel_launch(void* const* d_in, const int* in_sizes, int n_in,
                              void* d_out, int out_size) {
    (void)in_sizes; (void)n_in; (void)out_size;
    const float* x_in = (const float*)d_in[0];
    const int*   ei   = (const int*)d_in[1];
    const int*   src  = ei;
    const int*   dst  = ei + NEDGES;

    const float* cw[3] = {(const float*)d_in[2],  (const float*)d_in[8],  (const float*)d_in[14]};
    const float* cb[3] = {(const float*)d_in[3],  (const float*)d_in[9],  (const float*)d_in[15]};
    const float* aw[3] = {(const float*)d_in[4],  (const float*)d_in[10], (const float*)d_in[16]};
    const float* ab[3] = {(const float*)d_in[5],  (const float*)d_in[11], (const float*)d_in[17]};
    const float* rw[3] = {(const float*)d_in[6],  (const float*)d_in[12], (const float*)d_in[18]};
    const float* rb[3] = {(const float*)d_in[7],  (const float*)d_in[13], (const float*)d_in[19]};
    const float* gam[2] = {(const float*)d_in[20], (const float*)d_in[22]};
    const float* bet[2] = {(const float*)d_in[21], (const float*)d_in[23]};
    float* out = (float*)d_out;

    float *p_x, *p_h, *p_t;
    __half *p_xa, *p_ca, *p_wh, *p_wl;
    cudaGetSymbolAddress((void**)&p_x, g_x);
    cudaGetSymbolAddress((void**)&p_h, g_h);
    cudaGetSymbolAddress((void**)&p_t, g_t);
    cudaGetSymbolAddress((void**)&p_xa, g_xa);
    cudaGetSymbolAddress((void**)&p_ca, g_ca);
    cudaGetSymbolAddress((void**)&p_wh, g_wh);
    cudaGetSymbolAddress((void**)&p_wl, g_wl);

    const int SMB = 2 * STAGE_BYTES + 1024;

    static cudaStream_t s2 = nullptr, s3 = nullptr;
    static cudaEvent_t evFork = nullptr, evH = nullptr, evAgg = nullptr;
    static cudaEvent_t evW03 = nullptr, evW = nullptr;
    if (s2 == nullptr) {
        cudaFuncSetAttribute(mma_gemm, cudaFuncAttributeMaxDynamicSharedMemorySize, SMB);
        cudaFuncSetAttribute(mma_gemm_fused, cudaFuncAttributeMaxDynamicSharedMemorySize, SMB);
        cudaStreamCreateWithFlags(&s2, cudaStreamNonBlocking);
        cudaStreamCreateWithFlags(&s3, cudaStreamNonBlocking);
        cudaEventCreateWithFlags(&evFork, cudaEventDisableTiming);
        cudaEventCreateWithFlags(&evH, cudaEventDisableTiming);
        cudaEventCreateWithFlags(&evAgg, cudaEventDisableTiming);
        cudaEventCreateWithFlags(&evW03, cudaEventDisableTiming);
        cudaEventCreateWithFlags(&evW, cudaEventDisableTiming);
    }

    // ---- fork: CSR setup on s2, weight pre-split on s3 ----
    cudaEventRecord(evFork, 0);
    cudaStreamWaitEvent(s2, evFork, 0);
    cudaStreamWaitEvent(s3, evFork, 0);

    padzero_kernel<<<NNODES, 64, 0, s2>>>();
    zero_deg_kernel<<<(NNODES + 255) / 256, 256, 0, s2>>>();
    count_deg_kernel<<<800, 256, 0, s2>>>(dst);
    scan1_kernel<<<49, 1024, 0, s2>>>();
    scan2_kernel<<<1, 1, 0, s2>>>();
    scan3_kernel<<<49, 1024, 0, s2>>>();
    fill_csr_kernel<<<800, 256, 0, s2>>>(src, dst);

    const int dinv[3] = {128, 256, 256};
    for (int l = 0; l < 3; l++) {
        int K = dinv[l];
        int n1 = 256 * K;
        wsplit_kernel<<<(n1 + 255) / 256, 256, 0, s3>>>(cw[l], K, 256, 256, K, 3 * l, 0);
        int n2 = 448 * K;
        wsplit_kernel<<<(n2 + 255) / 256, 256, 0, s3>>>(aw[l], K, 400, 448, K, 3 * l, 256);
        int dout = (l < 2) ? 256 : 128;
        int n3 = dout * 512;
        wsplit_kernel<<<(n3 + 255) / 256, 256, 0, s3>>>(rw[l], 456, dout, dout, 512, 3 * l + 2, 0);
        if (l == 0) cudaEventRecord(evW03, s3);
    }
    cudaEventRecord(evW, s3);

    // ---- main stream: input conversion; wait only for layer-0 weights ----
    xsplit_kernel<<<(NNODES * 128 + 255) / 256, 256>>>(x_in, (long)NNODES * 128);
    cudaStreamWaitEvent(0, evW03, 0);

    for (int l = 0; l < 3; l++) {
        if (l == 1) cudaStreamWaitEvent(0, evW, 0);
        int din = dinv[l];
        const __half* sh = p_wh + (size_t)(3 * l) * WSLOT;
        const __half* sl = p_wl + (size_t)(3 * l) * WSLOT;
        const __half* rwh = p_wh + (size_t)(3 * l + 2) * WSLOT;
        const __half* rwl = p_wl + (size_t)(3 * l + 2) * WSLOT;

        // fused: h = x@cw ; t = relu(x@aw + ab)  (11 column tiles)
        mma_gemm_fused<<<dim3(11, MB), 256, SMB>>>(
            p_xa, sh, sl, ab[l], p_h, p_t, NNODES, din);
        cudaEventRecord(evH, 0);

        // side stream: aggregation
        cudaStreamWaitEvent(s2, evH, 0);
        agg_kernel<<<NNODES, HD, 0, s2>>>(cb[l]);
        cudaEventRecord(evAgg, s2);

        // main: low-rank path (vtz also produces colsum -> g_cs)
        zero_misc_kernel<<<(KLR * KLR + 255) / 256, 256>>>();
        vtz_kernel<<<200, 256>>>();
        nf_kernel<<<1, 32>>>();
        respack_kernel<<<(NNODES + 63) / 64, 256>>>();

        // join: combine needs agg output
        cudaStreamWaitEvent(0, evAgg, 0);
        if (l < 2) {
            mma_gemm<<<dim3(HD / 64, MB), 256, SMB>>>(
                p_ca, rwh, rwl, rb[l], p_x, NNODES, GDC, HD, HD, 1);
            bn_stats_kernel<<<(NNODES + 127) / 128, 256>>>();
            bn_apply_kernel<<<(NNODES * HD + 255) / 256, 256>>>(gam[l], bet[l]);
        } else {
            mma_gemm<<<dim3(2, MB), 256, SMB>>>(
                p_ca, rwh, rwl, rb[l], out, NNODES, GDC, 128, 128, 0);
        }
    }
}

// round 15
// speedup vs baseline: 1.5033x; 1.0775x over previous
#include <cuda_runtime.h>
#include <cuda_fp16.h>
#include <cstdint>

// ---------------- problem constants ----------------
#define NNODES 50000
#define NEDGES 800000
#define HD     256
#define TD2    512
#define GDC    512
#define KLR    100
#define MB     391
#define WSLOT  (512 * 512)

// ---------------- static scratch ----------------
__device__ float g_x[NNODES * HD];
__device__ float g_h[NNODES * HD];
__device__ float g_t[NNODES * TD2];
__device__ __half g_xa[NNODES * HD];
__device__ __half g_ca[NNODES * GDC];
__device__ __half g_wh[9 * WSLOT];
__device__ __half g_wl[9 * WSLOT];
__device__ float g_M[KLR * KLR];
__device__ float g_cs[2 * KLR];
__device__ float g_inv_nf;
__device__ int   g_ctr;
__device__ float g_mean[HD];
__device__ float g_msq[HD];
__device__ float g_dis[NNODES];
__device__ int   g_deg[NNODES];
__device__ int   g_rowptr[NNODES + 1];
__device__ int   g_cur[NNODES];
__device__ int   g_colidx[NEDGES];
__device__ int   g_bsum[64];

// ---------------- PTX helpers ----------------
__device__ __forceinline__ uint32_t smem_u32(const void* p) {
    uint32_t a;
    asm("{ .reg .u64 t; cvta.to.shared.u64 t, %1; cvt.u32.u64 %0, t; }"
        : "=r"(a) : "l"(p));
    return a;
}

__device__ __forceinline__ void cp16(uint32_t dst, const void* src, int sz) {
    asm volatile("cp.async.cg.shared.global [%0], [%1], 16, %2;"
                 :: "r"(dst), "l"(src), "r"(sz) : "memory");
}

__device__ __forceinline__ void ldm_x4(uint32_t* r, uint32_t addr) {
    asm volatile("ldmatrix.sync.aligned.m8n8.x4.shared.b16 {%0,%1,%2,%3}, [%4];"
                 : "=r"(r[0]), "=r"(r[1]), "=r"(r[2]), "=r"(r[3]) : "r"(addr));
}

__device__ __forceinline__ void mma_f16(float* d, const uint32_t* a,
                                        const uint32_t* b) {
    asm volatile(
        "mma.sync.aligned.m16n8k16.row.col.f32.f16.f16.f32 "
        "{%0,%1,%2,%3}, {%4,%5,%6,%7}, {%8,%9}, {%0,%1,%2,%3};"
        : "+f"(d[0]), "+f"(d[1]), "+f"(d[2]), "+f"(d[3])
        : "r"(a[0]), "r"(a[1]), "r"(a[2]), "r"(a[3]), "r"(b[0]), "r"(b[1]));
}

// ---------------- shared GEMM mainloop (fp16 2-product, round-14 proven) ----
#define STAGE_BYTES 32768

#define GEMM_MAINLOOP(ACC)                                                     \
    extern __shared__ char dsm_raw[];                                          \
    uint32_t base0 = (smem_u32(dsm_raw) + 1023u) & ~1023u;                     \
    const int tid = threadIdx.x;                                               \
    const int wid = tid >> 5;                                                  \
    const int lane = tid & 31;                                                 \
    const int wm = wid & 3;                                                    \
    const int wn = wid >> 2;                                                   \
    const int row0 = blockIdx.y * 128;                                         \
    const int col0 = blockIdx.x * 64;                                          \
    const __half* Bh0 = Bh + (size_t)col0 * K;                                 \
    const __half* Bl0 = Bl + (size_t)col0 * K;                                 \
    const int nc = K >> 6;                                                     \
    float ACC[2][4][4];                                                        \
    _Pragma("unroll")                                                          \
    for (int mt = 0; mt < 2; mt++)                                             \
        _Pragma("unroll")                                                      \
        for (int nt = 0; nt < 4; nt++)                                         \
            _Pragma("unroll")                                                  \
            for (int q = 0; q < 4; q++) ACC[mt][nt][q] = 0.f;                  \
    auto load_chunk = [&](int c) {                                             \
        uint32_t sb = base0 + (uint32_t)(c & 1) * STAGE_BYTES;                 \
        int k0 = c << 6;                                                       \
        _Pragma("unroll 4")                                                    \
        for (int j = 0; j < 4; j++) {                                          \
            int i = tid + j * 256;                                             \
            int r = i >> 3, seg = i & 7;                                       \
            int off = r * 128 + seg * 16;                                      \
            uint32_t sw = (uint32_t)(off ^ ((off >> 3) & 0x70));               \
            int ga = row0 + r;                                                 \
            int ok = (ga < M) ? 16 : 0;                                        \
            if (ga >= M) ga = 0;                                               \
            size_t ao = (size_t)ga * K + k0 + seg * 8;                         \
            cp16(sb + sw, A + ao, ok);                                         \
        }                                                                      \
        {                                                                      \
            int i = tid;                                                       \
            int r = i >> 3, seg = i & 7;                                       \
            int off = r * 128 + seg * 16;                                      \
            uint32_t sw = (uint32_t)(off ^ ((off >> 3) & 0x70));               \
            size_t bo = (size_t)r * K + k0 + seg * 8;                          \
            cp16(sb + 16384 + sw, Bh0 + bo, 16);                               \
            cp16(sb + 24576 + sw, Bl0 + bo, 16);                               \
        }                                                                      \
        {                                                                      \
            int i = tid + 256;                                                 \
            int r = i >> 3, seg = i & 7;                                       \
            int off = r * 128 + seg * 16;                                      \
            uint32_t sw = (uint32_t)(off ^ ((off >> 3) & 0x70));               \
            size_t bo = (size_t)r * K + k0 + seg * 8;                          \
            cp16(sb + 16384 + sw, Bh0 + bo, 16);                               \
            cp16(sb + 24576 + sw, Bl0 + bo, 16);                               \
        }                                                                      \
        asm volatile("cp.async.commit_group;" ::: "memory");                   \
    };                                                                         \
    const int a_off0 = (wm * 32 + (lane & 15)) * 128 + ((lane >> 4) << 4);     \
    const int b_off0 = (wn * 32 + ((lane >> 4) << 3) + (lane & 7)) * 128       \
                     + (((lane >> 3) & 1) << 4);                               \
    load_chunk(0);                                                             \
    for (int c = 0; c < nc; c++) {                                             \
        if (c + 1 < nc) {                                                      \
            load_chunk(c + 1);                                                 \
            asm volatile("cp.async.wait_group 1;" ::: "memory");               \
        } else {                                                               \
            asm volatile("cp.async.wait_group 0;" ::: "memory");               \
        }                                                                      \
        __syncthreads();                                                       \
        uint32_t sb = base0 + (uint32_t)(c & 1) * STAGE_BYTES;                 \
        _Pragma("unroll")                                                      \
        for (int kk = 0; kk < 4; kk++) {                                       \
            uint32_t ah[2][4], bh[2][4], bl[2][4];                             \
            _Pragma("unroll")                                                  \
            for (int mt = 0; mt < 2; mt++) {                                   \
                int off = a_off0 + mt * 2048 + kk * 32;                        \
                uint32_t sw = (uint32_t)(off ^ ((off >> 3) & 0x70));           \
                ldm_x4(ah[mt], sb + sw);                                       \
            }                                                                  \
            _Pragma("unroll")                                                  \
            for (int np = 0; np < 2; np++) {                                   \
                int off = b_off0 + np * 2048 + kk * 32;                        \
                uint32_t sw = (uint32_t)(off ^ ((off >> 3) & 0x70));           \
                ldm_x4(bh[np], sb + 16384 + sw);                               \
                ldm_x4(bl[np], sb + 24576 + sw);                               \
            }                                                                  \
            _Pragma("unroll")                                                  \
            for (int mt = 0; mt < 2; mt++)                                     \
                _Pragma("unroll")                                              \
                for (int nt = 0; nt < 4; nt++) {                               \
                    const uint32_t* bhp = &bh[nt >> 1][(nt & 1) * 2];          \
                    const uint32_t* blp = &bl[nt >> 1][(nt & 1) * 2];          \
                    mma_f16(ACC[mt][nt], ah[mt], bhp);                         \
                    mma_f16(ACC[mt][nt], ah[mt], blp);                         \
                }                                                              \
        }                                                                      \
        __syncthreads();                                                       \
    }

// ---------------- plain GEMM: C = act(A@B^T + bias) ----------------
__global__ void __launch_bounds__(256, 2)
mma_gemm(const __half* __restrict__ A,
         const __half* __restrict__ Bh, const __half* __restrict__ Bl,
         const float* __restrict__ bias, float* __restrict__ C,
         int M, int K, int ldc, int nvalid, int relu) {
    GEMM_MAINLOOP(acc)
#pragma unroll
    for (int mt = 0; mt < 2; mt++) {
        int ra = row0 + wm * 32 + mt * 16 + (lane >> 2);
        int rb = ra + 8;
#pragma unroll
        for (int nt = 0; nt < 4; nt++) {
            int c0 = col0 + wn * 32 + nt * 8 + (lane & 3) * 2;
            float bv0 = 0.f, bv1 = 0.f;
            if (bias && c0 < nvalid) {
                bv0 = __ldg(&bias[c0]);
                bv1 = __ldg(&bias[c0 + 1]);
            }
            float v0 = acc[mt][nt][0] + bv0;
            float v1 = acc[mt][nt][1] + bv1;
            float v2 = acc[mt][nt][2] + bv0;
            float v3 = acc[mt][nt][3] + bv1;
            if (relu) {
                v0 = fmaxf(v0, 0.f); v1 = fmaxf(v1, 0.f);
                v2 = fmaxf(v2, 0.f); v3 = fmaxf(v3, 0.f);
            }
            if (ra < M) *(float2*)&C[(size_t)ra * ldc + c0] = make_float2(v0, v1);
            if (rb < M) *(float2*)&C[(size_t)rb * ldc + c0] = make_float2(v2, v3);
        }
    }
}

// ---------------- fused h+t GEMM ----------------
__global__ void __launch_bounds__(256, 2)
mma_gemm_fused(const __half* __restrict__ A,
               const __half* __restrict__ Bh, const __half* __restrict__ Bl,
               const float* __restrict__ bias2,
               float* __restrict__ C1, float* __restrict__ C2,
               int M, int K) {
    GEMM_MAINLOOP(acc)
    float* C;
    int ldc, rel, cbase, nval;
    const float* bias;
    if (col0 < 256) {
        C = C1; ldc = HD; rel = 0; bias = nullptr; cbase = col0; nval = HD;
    } else {
        C = C2; ldc = TD2; rel = 1; bias = bias2; cbase = col0 - 256; nval = 400;
    }
#pragma unroll
    for (int mt = 0; mt < 2; mt++) {
        int ra = row0 + wm * 32 + mt * 16 + (lane >> 2);
        int rb = ra + 8;
#pragma unroll
        for (int nt = 0; nt < 4; nt++) {
            int c0 = cbase + wn * 32 + nt * 8 + (lane & 3) * 2;
            float bv0 = 0.f, bv1 = 0.f;
            if (bias && c0 < nval) {
                bv0 = __ldg(&bias[c0]);
                bv1 = __ldg(&bias[c0 + 1]);
            }
            float v0 = acc[mt][nt][0] + bv0;
            float v1 = acc[mt][nt][1] + bv1;
            float v2 = acc[mt][nt][2] + bv0;
            float v3 = acc[mt][nt][3] + bv1;
            if (rel) {
                v0 = fmaxf(v0, 0.f); v1 = fmaxf(v1, 0.f);
                v2 = fmaxf(v2, 0.f); v3 = fmaxf(v3, 0.f);
            }
            if (ra < M) *(float2*)&C[(size_t)ra * ldc + c0] = make_float2(v0, v1);
            if (rb < M) *(float2*)&C[(size_t)rb * ldc + c0] = make_float2(v2, v3);
        }
    }
}

// ---------------- conversion kernels ----------------
__global__ void xsplit_kernel(const float* __restrict__ x, long n) {
    long i = (long)blockIdx.x * blockDim.x + threadIdx.x;
    if (i < n) g_xa[i] = __float2half(x[i]);
}

__global__ void wsplit_kernel(const float* __restrict__ W, int K, int N,
                              int Nout, int Kpad, int slot, int row0) {
    int i = blockIdx.x * blockDim.x + threadIdx.x;
    if (i < Nout * Kpad) {
        int n = i / Kpad, k = i - n * Kpad;
        float v = (n < N && k < K) ? W[(size_t)k * N + n] : 0.f;
        __half hi = __float2half(v);
        size_t o = (size_t)slot * WSLOT + (size_t)(row0 + n) * Kpad + k;
        g_wh[o] = hi;
        g_wl[o] = __float2half(v - __half2float(hi));
    }
}

__global__ void padzero_kernel() {
    int v = blockIdx.x, c = threadIdx.x;
    if (c < GDC - 456) {
        size_t o = (size_t)v * GDC + 456 + c;
        g_ca[o] = __float2half(0.f);
    }
}

// ---------------- graph setup ----------------
__global__ void zero_deg_kernel() {
    int i = blockIdx.x * blockDim.x + threadIdx.x;
    if (i < NNODES) g_deg[i] = 0;
}

__global__ void count_deg_kernel(const int* __restrict__ dst) {
    for (int e = blockIdx.x * blockDim.x + threadIdx.x; e < NEDGES;
         e += gridDim.x * blockDim.x)
        atomicAdd(&g_deg[dst[e]], 1);
}

__global__ void scan1_kernel() {
    __shared__ int s[1024];
    int tid = threadIdx.x;
    int i = blockIdx.x * 1024 + tid;
    int v = (i < NNODES) ? g_deg[i] : 0;
    s[tid] = v;
    __syncthreads();
    for (int off = 1; off < 1024; off <<= 1) {
        int t = (tid >= off) ? s[tid - off] : 0;
        __syncthreads();
        s[tid] += t;
        __syncthreads();
    }
    if (i < NNODES) g_rowptr[i + 1] = s[tid];
    if (tid == 1023) g_bsum[blockIdx.x] = s[1023];
}

__global__ void scan2_kernel() {
    int acc = 0;
    for (int b = 0; b < 49; b++) { int t = g_bsum[b]; g_bsum[b] = acc; acc += t; }
}

__global__ void scan3_kernel() {
    int i = blockIdx.x * 1024 + threadIdx.x;
    if (i == 0) g_rowptr[0] = 0;
    if (i < NNODES) {
        int incl = g_rowptr[i + 1] + g_bsum[blockIdx.x];
        g_rowptr[i + 1] = incl;
        g_cur[i] = incl - g_deg[i];
        g_dis[i] = rsqrtf((float)(g_deg[i] + 1));
    }
}

__global__ void fill_csr_kernel(const int* __restrict__ src,
                                const int* __restrict__ dst) {
    for (int e = blockIdx.x * blockDim.x + threadIdx.x; e < NEDGES;
         e += gridDim.x * blockDim.x) {
        int d = dst[e];
        int p = atomicAdd(&g_cur[d], 1);
        g_colidx[p] = src[e];
    }
}

// ---------------- low-rank path ----------------
__global__ void zero_misc_kernel() {
    int i = blockIdx.x * blockDim.x + threadIdx.x;
    if (i < KLR * KLR) g_M[i] = 0.f;
    if (i < 2 * KLR)   g_cs[i] = 0.f;
    if (i < HD)        { g_mean[i] = 0.f; g_msq[i] = 0.f; }
    if (i == 0)        g_ctr = 0;
}

// M = V^T @ Z + column sums of U,V fused; last block computes inv_nf.
// 400 k-split blocks x 125 rows, 7x7 register tile per thread.
#define VTZ_BLOCKS 400
__global__ void __launch_bounds__(256) vtz_kernel() {
    __shared__ float Us[32][112];
    __shared__ float Vs[32][112];
    __shared__ float Zs[32][112];
    __shared__ int s_last;
    const int tid = threadIdx.x;
    const int i = tid >> 4;
    const int j = tid & 15;
    const int kbeg = blockIdx.x * 125;
    const int kend = min(kbeg + 125, NNODES);

    float acc[7][7];
#pragma unroll
    for (int p = 0; p < 7; p++)
#pragma unroll
        for (int q = 0; q < 7; q++) acc[p][q] = 0.f;
    float csum = 0.f;

    for (int k0 = kbeg; k0 < kend; k0 += 32) {
        int km = kend - k0;
        for (int idx = tid; idx < 32 * 112; idx += 256) {
            int kk = idx / 112, cc = idx - kk * 112;
            float u = 0.f, v = 0.f, z = 0.f;
            if (kk < km && cc < KLR) {
                size_t b = (size_t)(k0 + kk) * TD2;
                u = g_t[b + cc];
                v = g_t[b + KLR + cc];
                z = g_t[b + 2 * KLR + cc];
            }
            Us[kk][cc] = u;
            Vs[kk][cc] = v;
            Zs[kk][cc] = z;
        }
        __syncthreads();
        if (tid < 2 * KLR) {
            float s = 0.f;
#pragma unroll 8
            for (int kk = 0; kk < 32; kk++)
                s += (tid < KLR) ? Us[kk][tid] : Vs[kk][tid - KLR];
            csum += s;
        }
#pragma unroll 4
        for (int kk = 0; kk < 32; kk++) {
            float av[7], bz[7];
#pragma unroll
            for (int p = 0; p < 7; p++) av[p] = Vs[kk][i + 16 * p];
#pragma unroll
            for (int q = 0; q < 7; q++) bz[q] = Zs[kk][j + 16 * q];
#pragma unroll
            for (int p = 0; p < 7; p++)
#pragma unroll
                for (int q = 0; q < 7; q++)
                    acc[p][q] = fmaf(av[p], bz[q], acc[p][q]);
        }
        __syncthreads();
    }
    if (tid < 2 * KLR) atomicAdd(&g_cs[tid], csum);
#pragma unroll
    for (int p = 0; p < 7; p++) {
        int r = i + 16 * p;
        if (r >= KLR) break;
#pragma unroll
        for (int q = 0; q < 7; q++) {
            int c = j + 16 * q;
            if (c < KLR) atomicAdd(&g_M[r * KLR + c], acc[p][q]);
        }
    }
    // last block computes inv_nf from completed g_cs
    __threadfence();
    __syncthreads();
    if (tid == 0) s_last = (atomicAdd(&g_ctr, 1) == VTZ_BLOCKS - 1) ? 1 : 0;
    __syncthreads();
    if (s_last && tid < 32) {
        float s = 0.f;
        for (int k = tid; k < KLR; k += 32)
            s += __ldcg(&g_cs[k]) * __ldcg(&g_cs[KLR + k]);
#pragma unroll
        for (int o = 16; o > 0; o >>= 1) s += __shfl_down_sync(0xffffffffu, s, o);
        if (tid == 0) g_inv_nf = 1.0f / (s / (float)NNODES + 1e-6f);
    }
}

// combine cols 0..199 = [res/nf | T] as fp16; 64 rows/block, 4x7 tile/thread
__global__ void __launch_bounds__(256) respack_kernel() {
    __shared__ float Msh[KLR * KLR];
    __shared__ float Ush[64][KLR];
    int tid = threadIdx.x;
    int r0 = blockIdx.x * 64;
    for (int idx = tid; idx < KLR * KLR; idx += 256) Msh[idx] = g_M[idx];
    for (int idx = tid; idx < 64 * KLR; idx += 256) {
        int r = idx / KLR, c = idx - r * KLR;
        Ush[r][c] = (r0 + r < NNODES) ? g_t[(size_t)(r0 + r) * TD2 + c] : 0.f;
    }
    __syncthreads();
    float inv = g_inv_nf;
    int rg = tid >> 4;
    int cg = tid & 15;

    float acc[4][7];
#pragma unroll
    for (int jj = 0; jj < 4; jj++)
#pragma unroll
        for (int q = 0; q < 7; q++) acc[jj][q] = 0.f;

    for (int k = 0; k < KLR; k++) {
        float m[7];
#pragma unroll
        for (int q = 0; q < 7; q++) {
            int c = cg + 16 * q;
            m[q] = (c < KLR) ? Msh[k * KLR + c] : 0.f;
        }
#pragma unroll
        for (int jj = 0; jj < 4; jj++) {
            float a = Ush[rg + 16 * jj][k];
#pragma unroll
            for (int q = 0; q < 7; q++)
                acc[jj][q] = fmaf(a, m[q], acc[jj][q]);
        }
    }
#pragma unroll
    for (int jj = 0; jj < 4; jj++) {
        int r = r0 + rg + 16 * jj;
        if (r >= NNODES) continue;
        size_t base = (size_t)r * GDC;
#pragma unroll
        for (int q = 0; q < 7; q++) {
            int c = cg + 16 * q;
            if (c < KLR) g_ca[base + c] = __float2half(acc[jj][q] * inv);
        }
#pragma unroll
        for (int q = 0; q < 7; q++) {
            int c = cg + 16 * q;
            if (c < KLR)
                g_ca[base + KLR + c] =
                    __float2half(g_t[(size_t)r * TD2 + 3 * KLR + c]);
        }
    }
}

// combine cols 200..455 = relu(aggregate + cb) as fp16
__global__ void agg_kernel(const float* __restrict__ cb) {
    __shared__ int   sh_u[64];
    __shared__ float sh_w[64];
    const int v = blockIdx.x;
    const int c = threadIdx.x;
    const float dv = g_dis[v];
    float acc = g_h[(size_t)v * HD + c] * dv * dv;
    const int s0 = g_rowptr[v], e0 = g_rowptr[v + 1];
    for (int s = s0; s < e0; s += 64) {
        int m = min(64, e0 - s);
        __syncthreads();
        if (c < m) {
            int u = g_colidx[s + c];
            sh_u[c] = u;
            sh_w[c] = g_dis[u] * dv;
        }
        __syncthreads();
        int j = 0;
        for (; j + 4 <= m; j += 4) {
            float h0 = g_h[(size_t)sh_u[j + 0] * HD + c];
            float h1 = g_h[(size_t)sh_u[j + 1] * HD + c];
            float h2 = g_h[(size_t)sh_u[j + 2] * HD + c];
            float h3 = g_h[(size_t)sh_u[j + 3] * HD + c];
            acc = fmaf(h0, sh_w[j + 0], acc);
            acc = fmaf(h1, sh_w[j + 1], acc);
            acc = fmaf(h2, sh_w[j + 2], acc);
            acc = fmaf(h3, sh_w[j + 3], acc);
        }
        for (; j < m; j++)
            acc = fmaf(g_h[(size_t)sh_u[j] * HD + c], sh_w[j], acc);
    }
    acc = fmaxf(acc + cb[c], 0.f);
    g_ca[(size_t)v * GDC + 200 + c] = __float2half(acc);
}

// ---------------- batch norm ----------------
__global__ void bn_stats_kernel() {
    int col = threadIdx.x;
    int r0 = blockIdx.x * 128;
    int rend = min(r0 + 128, NNODES);
    float s = 0.f, s2 = 0.f;
    int r = r0;
    for (; r + 4 <= rend; r += 4) {
        float v0 = g_x[(size_t)(r + 0) * HD + col];
        float v1 = g_x[(size_t)(r + 1) * HD + col];
        float v2 = g_x[(size_t)(r + 2) * HD + col];
        float v3 = g_x[(size_t)(r + 3) * HD + col];
        s += v0 + v1 + v2 + v3;
        s2 = fmaf(v0, v0, s2);
        s2 = fmaf(v1, v1, s2);
        s2 = fmaf(v2, v2, s2);
        s2 = fmaf(v3, v3, s2);
    }
    for (; r < rend; r++) {
        float v = g_x[(size_t)r * HD + col];
        s += v;
        s2 = fmaf(v, v, s2);
    }
    atomicAdd(&g_mean[col], s);
    atomicAdd(&g_msq[col], s2);
}

__global__ void bn_apply_kernel(const float* __restrict__ gam,
                                const float* __restrict__ bet) {
    size_t i = (size_t)blockIdx.x * blockDim.x + threadIdx.x;
    if (i < (size_t)NNODES * HD) {
        int c = (int)(i & (HD - 1));
        float m = g_mean[c] * (1.f / NNODES);
        float var = g_msq[c] * (1.f / NNODES) - m * m;
        float sc = __ldg(&gam[c]) * rsqrtf(var + 1e-5f);
        float sh = __ldg(&bet[c]) - m * sc;
        g_xa[i] = __float2half(fmaf(g_x[i], sc, sh));
    }
}

// ---------------- host orchestration ----------------
extern "C" void kernel_launch(void* const* d_in, const int* in_sizes, int n_in,
                              void* d_out, int out_size) {
    (void)in_sizes; (void)n_in; (void)out_size;
    const float* x_in = (const float*)d_in[0];
    const int*   ei   = (const int*)d_in[1];
    const int*   src  = ei;
    const int*   dst  = ei + NEDGES;

    const float* cw[3] = {(const float*)d_in[2],  (const float*)d_in[8],  (const float*)d_in[14]};
    const float* cb[3] = {(const float*)d_in[3],  (const float*)d_in[9],  (const float*)d_in[15]};
    const float* aw[3] = {(const float*)d_in[4],  (const float*)d_in[10], (const float*)d_in[16]};
    const float* ab[3] = {(const float*)d_in[5],  (const float*)d_in[11], (const float*)d_in[17]};
    const float* rw[3] = {(const float*)d_in[6],  (const float*)d_in[12], (const float*)d_in[18]};
    const float* rb[3] = {(const float*)d_in[7],  (const float*)d_in[13], (const float*)d_in[19]};
    const float* gam[2] = {(const float*)d_in[20], (const float*)d_in[22]};
    const float* bet[2] = {(const float*)d_in[21], (const float*)d_in[23]};
    float* out = (float*)d_out;

    float *p_x, *p_h, *p_t;
    __half *p_xa, *p_ca, *p_wh, *p_wl;
    cudaGetSymbolAddress((void**)&p_x, g_x);
    cudaGetSymbolAddress((void**)&p_h, g_h);
    cudaGetSymbolAddress((void**)&p_t, g_t);
    cudaGetSymbolAddress((void**)&p_xa, g_xa);
    cudaGetSymbolAddress((void**)&p_ca, g_ca);
    cudaGetSymbolAddress((void**)&p_wh, g_wh);
    cudaGetSymbolAddress((void**)&p_wl, g_wl);

    const int SMB = 2 * STAGE_BYTES + 1024;

    static cudaStream_t s2 = nullptr, s3 = nullptr;
    static cudaEvent_t evFork = nullptr, evH = nullptr, evAgg = nullptr;
    static cudaEvent_t evW03 = nullptr, evW = nullptr;
    if (s2 == nullptr) {
        cudaFuncSetAttribute(mma_gemm, cudaFuncAttributeMaxDynamicSharedMemorySize, SMB);
        cudaFuncSetAttribute(mma_gemm_fused, cudaFuncAttributeMaxDynamicSharedMemorySize, SMB);
        cudaStreamCreateWithFlags(&s2, cudaStreamNonBlocking);
        cudaStreamCreateWithFlags(&s3, cudaStreamNonBlocking);
        cudaEventCreateWithFlags(&evFork, cudaEventDisableTiming);
        cudaEventCreateWithFlags(&evH, cudaEventDisableTiming);
        cudaEventCreateWithFlags(&evAgg, cudaEventDisableTiming);
        cudaEventCreateWithFlags(&evW03, cudaEventDisableTiming);
        cudaEventCreateWithFlags(&evW, cudaEventDisableTiming);
    }

    // ---- fork: CSR setup on s2, weight pre-split on s3 ----
    cudaEventRecord(evFork, 0);
    cudaStreamWaitEvent(s2, evFork, 0);
    cudaStreamWaitEvent(s3, evFork, 0);

    padzero_kernel<<<NNODES, 64, 0, s2>>>();
    zero_deg_kernel<<<(NNODES + 255) / 256, 256, 0, s2>>>();
    count_deg_kernel<<<800, 256, 0, s2>>>(dst);
    scan1_kernel<<<49, 1024, 0, s2>>>();
    scan2_kernel<<<1, 1, 0, s2>>>();
    scan3_kernel<<<49, 1024, 0, s2>>>();
    fill_csr_kernel<<<800, 256, 0, s2>>>(src, dst);

    const int dinv[3] = {128, 256, 256};
    for (int l = 0; l < 3; l++) {
        int K = dinv[l];
        int n1 = 256 * K;
        wsplit_kernel<<<(n1 + 255) / 256, 256, 0, s3>>>(cw[l], K, 256, 256, K, 3 * l, 0);
        int n2 = 448 * K;
        wsplit_kernel<<<(n2 + 255) / 256, 256, 0, s3>>>(aw[l], K, 400, 448, K, 3 * l, 256);
        int dout = (l < 2) ? 256 : 128;
        int n3 = dout * 512;
        wsplit_kernel<<<(n3 + 255) / 256, 256, 0, s3>>>(rw[l], 456, dout, dout, 512, 3 * l + 2, 0);
        if (l == 0) cudaEventRecord(evW03, s3);
    }
    cudaEventRecord(evW, s3);

    // ---- main stream: input conversion; wait only for layer-0 weights ----
    xsplit_kernel<<<(NNODES * 128 + 255) / 256, 256>>>(x_in, (long)NNODES * 128);
    cudaStreamWaitEvent(0, evW03, 0);

    for (int l = 0; l < 3; l++) {
        if (l == 1) cudaStreamWaitEvent(0, evW, 0);
        int din = dinv[l];
        const __half* sh = p_wh + (size_t)(3 * l) * WSLOT;
        const __half* sl = p_wl + (size_t)(3 * l) * WSLOT;
        const __half* rwh = p_wh + (size_t)(3 * l + 2) * WSLOT;
        const __half* rwl = p_wl + (size_t)(3 * l + 2) * WSLOT;

        // fused: h = x@cw ; t = relu(x@aw + ab)  (11 column tiles)
        mma_gemm_fused<<<dim3(11, MB), 256, SMB>>>(
            p_xa, sh, sl, ab[l], p_h, p_t, NNODES, din);
        cudaEventRecord(evH, 0);

        // side stream: aggregation
        cudaStreamWaitEvent(s2, evH, 0);
        agg_kernel<<<NNODES, HD, 0, s2>>>(cb[l]);
        cudaEventRecord(evAgg, s2);

        // main: low-rank path (vtz produces colsum + inv_nf internally)
        zero_misc_kernel<<<(KLR * KLR + 255) / 256, 256>>>();
        vtz_kernel<<<VTZ_BLOCKS, 256>>>();
        respack_kernel<<<(NNODES + 63) / 64, 256>>>();

        // join: combine needs agg output
        cudaStreamWaitEvent(0, evAgg, 0);
        if (l < 2) {
            mma_gemm<<<dim3(HD / 64, MB), 256, SMB>>>(
                p_ca, rwh, rwl, rb[l], p_x, NNODES, GDC, HD, HD, 1);
            bn_stats_kernel<<<(NNODES + 127) / 128, 256>>>();
            bn_apply_kernel<<<(NNODES * HD + 255) / 256, 256>>>(gam[l], bet[l]);
        } else {
            mma_gemm<<<dim3(2, MB), 256, SMB>>>(
                p_ca, rwh, rwl, rb[l], out, NNODES, GDC, 128, 128, 0);
        }
    }
}